// round 1
// baseline (speedup 1.0000x reference)
#include <cuda_runtime.h>
#include <cuda_bf16.h>
#include <math.h>

// Problem constants
#define NB   32      // graphs
#define NPG0 128     // nodes per graph initially
#define NE   8192    // edges
#define CIN0 64      // input node feat
#define ED   32      // edge feat
#define HH   128     // hidden
#define CED  33      // ED + 1 bias slice
#define YC   (CED*HH)   // 4224 y columns
#define K1   64
#define K2   32
#define K3   16
#define NN0  (NB*NPG0)  // 4096

// ---------------- scratch (device globals; no allocation) ----------------
__device__ float g_y[NN0 * YC];         // per-node precomputed x @ W' (69 MB)
__device__ float g_h[NN0 * HH];         // pooled node features
__device__ float g_h2[NN0 * HH];        // conv output / agg buffer
__device__ float g_score[NN0];
__device__ int   g_map[NN0];
__device__ int   g_perm[NN0];
__device__ int   g_src[NE], g_dst[NE], g_valid[NE];
__device__ float g_stats[2 * HH];       // per-channel sum, sumsq
__device__ float g_pwn[1];
__device__ float g_gpool[NB * HH];

// ---------------- kernels ----------------

__global__ void init_edges_k(const int* __restrict__ ei,
                             int* __restrict__ src, int* __restrict__ dst,
                             int* __restrict__ valid) {
    int e = blockIdx.x * blockDim.x + threadIdx.x;
    if (e < NE) {
        src[e] = ei[e];
        dst[e] = ei[NE + e];
        valid[e] = 1;
    }
}

// Y[n, 4224] = A[n, cin] @ B  where B[k, d*128+o] = (d<32 ? W[d*cin*128 + k*128 + o]
//                                                          : bvec[k*128+o])
// BM=128, BN=128 (== one d slice), BK=8, 256 threads, 8x8 per thread.
__global__ void gemm_y_k(const float* __restrict__ A, const float* __restrict__ W,
                         const float* __restrict__ bvec, float* __restrict__ Y,
                         int n, int cin) {
    __shared__ float As[8][128];
    __shared__ float Bs[8][128];
    const int brow = blockIdx.y * 128;
    const int d = blockIdx.x;                 // 0..32 -> bcol = d*128
    const float* Bsrc = (d < ED) ? (W + (size_t)d * cin * HH) : bvec;
    const int tid = threadIdx.x;
    const int tr = tid >> 4;                  // 0..15
    const int tc = tid & 15;                  // 0..15

    float acc[8][8];
#pragma unroll
    for (int i = 0; i < 8; i++)
#pragma unroll
        for (int j = 0; j < 8; j++) acc[i][j] = 0.f;

    for (int k0 = 0; k0 < cin; k0 += 8) {
        // A tile: 128 rows x 8 k (transposed into As[k][row])
#pragma unroll
        for (int i = tid; i < 1024; i += 256) {
            int r = i >> 3, k = i & 7;
            int row = brow + r;
            As[k][r] = (row < n) ? A[(size_t)row * cin + k0 + k] : 0.f;
        }
        // B tile: 8 k x 128 o
#pragma unroll
        for (int i = tid; i < 1024; i += 256) {
            int k = i >> 7, o = i & 127;
            Bs[k][o] = Bsrc[(size_t)(k0 + k) * HH + o];
        }
        __syncthreads();
#pragma unroll
        for (int k = 0; k < 8; k++) {
            float a[8], b[8];
#pragma unroll
            for (int i = 0; i < 8; i++) a[i] = As[k][tr * 8 + i];
#pragma unroll
            for (int j = 0; j < 8; j++) b[j] = Bs[k][tc * 8 + j];
#pragma unroll
            for (int i = 0; i < 8; i++)
#pragma unroll
                for (int j = 0; j < 8; j++) acc[i][j] = fmaf(a[i], b[j], acc[i][j]);
        }
        __syncthreads();
    }
#pragma unroll
    for (int i = 0; i < 8; i++) {
        int row = brow + tr * 8 + i;
        if (row >= n) continue;
        float* yr = Y + (size_t)row * YC + d * HH + tc * 8;
#pragma unroll
        for (int j = 0; j < 8; j++) yr[j] = acc[i][j];
    }
}

// agg[v, o] = bias[o] + sum_i h[v,i] * root[i*128+o]
__global__ void root_init_k(const float* __restrict__ h, const float* __restrict__ root,
                            const float* __restrict__ bias, float* __restrict__ out,
                            int cin) {
    __shared__ float sh[HH];
    int v = blockIdx.x, o = threadIdx.x;
    for (int i = o; i < cin; i += HH) sh[i] = h[(size_t)v * cin + i];
    __syncthreads();
    float acc = bias[o];
    for (int i = 0; i < cin; i++) acc = fmaf(sh[i], root[i * HH + o], acc);
    out[(size_t)v * HH + o] = acc;
}

// per edge: agg[dst] += sum_{d<33} a[e,d] * y[src, d*128 + o]
__global__ void edge_msg_k(const float* __restrict__ ea, const float* __restrict__ y,
                           float* __restrict__ agg,
                           const int* __restrict__ src, const int* __restrict__ dst,
                           const int* __restrict__ valid) {
    int e = blockIdx.x;
    if (!valid[e]) return;
    __shared__ float a[CED];
    int o = threadIdx.x;
    if (o < ED) a[o] = ea[(size_t)e * ED + o];
    if (o == ED) a[ED] = 1.f;
    __syncthreads();
    const float* yr = y + (size_t)src[e] * YC + o;
    float acc = 0.f;
#pragma unroll
    for (int d = 0; d < CED; d++) acc = fmaf(a[d], yr[d * HH], acc);
    atomicAdd(&agg[(size_t)dst[e] * HH + o], acc);
}

__global__ void zero_stats_k(float* __restrict__ stats) {
    int i = threadIdx.x;
    if (i < 2 * HH) stats[i] = 0.f;
}

__global__ void bn_stats_k(const float* __restrict__ h, float* __restrict__ stats, int n) {
    int ch = threadIdx.x;
    float s = 0.f, s2 = 0.f;
    for (int r = blockIdx.x; r < n; r += gridDim.x) {
        float v = h[(size_t)r * HH + ch];
        s += v; s2 += v * v;
    }
    atomicAdd(&stats[ch], s);
    atomicAdd(&stats[HH + ch], s2);
}

__global__ void pwnorm_k(const float* __restrict__ pw, float* __restrict__ pwn) {
    __shared__ float red[HH];
    int i = threadIdx.x;
    float v = pw[i];
    red[i] = v * v;
    __syncthreads();
    for (int st = 64; st > 0; st >>= 1) {
        if (i < st) red[i] += red[i + st];
        __syncthreads();
    }
    if (i == 0) pwn[0] = sqrtf(red[0]);
}

// in-place BN + ReLU + pooling score
__global__ void bn_apply_score_k(float* __restrict__ h, const float* __restrict__ gamma,
                                 const float* __restrict__ beta, const float* __restrict__ pw,
                                 const float* __restrict__ stats, const float* __restrict__ pwn,
                                 float* __restrict__ score, int n) {
    __shared__ float red[HH];
    int v = blockIdx.x, o = threadIdx.x;
    float inv_n = 1.f / (float)n;
    float mu = stats[o] * inv_n;
    float var = stats[HH + o] * inv_n - mu * mu;
    float val = gamma[o] * (h[(size_t)v * HH + o] - mu) * rsqrtf(var + 1e-5f) + beta[o];
    val = fmaxf(val, 0.f);
    h[(size_t)v * HH + o] = val;
    red[o] = val * pw[o];
    __syncthreads();
    for (int st = 64; st > 0; st >>= 1) {
        if (o < st) red[o] += red[o + st];
        __syncthreads();
    }
    if (o == 0) score[v] = tanhf(red[0] / pwn[0]);
}

// one block per graph; npg threads; keep node iff rank<k; rank = new local id
__global__ void topk_k(const float* __restrict__ score, int* __restrict__ map,
                       int* __restrict__ perm, int npg, int k) {
    __shared__ float s[NPG0];
    int b = blockIdx.x, i = threadIdx.x;
    int base = b * npg;
    s[i] = score[base + i];
    __syncthreads();
    float mine = s[i];
    int rank = 0;
    for (int j = 0; j < npg; j++) {
        float sj = s[j];
        rank += (sj > mine) || (sj == mine && j < i);
    }
    if (rank < k) {
        int nid = b * k + rank;
        perm[nid] = base + i;
        map[base + i] = nid;
    } else {
        map[base + i] = -1;
    }
}

__global__ void gather_k(const float* __restrict__ hin, float* __restrict__ hout,
                         const int* __restrict__ perm, const float* __restrict__ score) {
    int v = blockIdx.x, o = threadIdx.x;
    int old = perm[v];
    hout[(size_t)v * HH + o] = hin[(size_t)old * HH + o] * score[old];
}

__global__ void remap_k(int* __restrict__ src, int* __restrict__ dst,
                        int* __restrict__ valid, const int* __restrict__ map) {
    int e = blockIdx.x * blockDim.x + threadIdx.x;
    if (e >= NE) return;
    if (valid[e]) {
        int ns = map[src[e]], nd = map[dst[e]];
        if (ns >= 0 && nd >= 0) { src[e] = ns; dst[e] = nd; }
        else valid[e] = 0;
    }
}

__global__ void meanpool_k(const float* __restrict__ h, float* __restrict__ g) {
    int b = blockIdx.x, o = threadIdx.x;
    float acc = 0.f;
#pragma unroll
    for (int i = 0; i < K3; i++) acc += h[(size_t)(b * K3 + i) * HH + o];
    g[b * HH + o] = acc * (1.f / K3);
}

__global__ void mlp_k(const float* __restrict__ g, const float* __restrict__ w1,
                      const float* __restrict__ b1, const float* __restrict__ w2,
                      const float* __restrict__ b2, float* __restrict__ out) {
    __shared__ float sg[HH];
    __shared__ float red[64];
    int b = blockIdx.x, j = threadIdx.x;  // 64 threads
    sg[j] = g[b * HH + j];
    sg[j + 64] = g[b * HH + 64 + j];
    __syncthreads();
    float acc = b1[j];
    for (int i = 0; i < HH; i++) acc = fmaf(sg[i], w1[i * 64 + j], acc);
    acc = fmaxf(acc, 0.f);
    red[j] = acc * w2[j];
    __syncthreads();
    for (int st = 32; st > 0; st >>= 1) {
        if (j < st) red[j] += red[j + st];
        __syncthreads();
    }
    if (j == 0) out[b] = 1.f / (1.f + expf(-(red[0] + b2[0])));
}

// ---------------- host ----------------

extern "C" void kernel_launch(void* const* d_in, const int* in_sizes, int n_in,
                              void* d_out, int out_size) {
    const float* x     = (const float*)d_in[0];
    const int*   ei    = (const int*)d_in[1];
    const float* ea    = (const float*)d_in[2];
    const float* nn1_w = (const float*)d_in[4];
    const float* nn1_b = (const float*)d_in[5];
    const float* root1 = (const float*)d_in[6];
    const float* bias1 = (const float*)d_in[7];
    const float* nn2_w = (const float*)d_in[8];
    const float* nn2_b = (const float*)d_in[9];
    const float* root2 = (const float*)d_in[10];
    const float* bias2 = (const float*)d_in[11];
    const float* nn3_w = (const float*)d_in[12];
    const float* nn3_b = (const float*)d_in[13];
    const float* root3 = (const float*)d_in[14];
    const float* bias3 = (const float*)d_in[15];
    const float* gamma1 = (const float*)d_in[16];
    const float* beta1  = (const float*)d_in[17];
    const float* gamma2 = (const float*)d_in[18];
    const float* beta2  = (const float*)d_in[19];
    const float* gamma3 = (const float*)d_in[20];
    const float* beta3  = (const float*)d_in[21];
    const float* pw1 = (const float*)d_in[22];
    const float* pw2 = (const float*)d_in[23];
    const float* pw3 = (const float*)d_in[24];
    const float* l1w = (const float*)d_in[25];
    const float* l1b = (const float*)d_in[26];
    const float* l2w = (const float*)d_in[27];
    const float* l2b = (const float*)d_in[28];
    float* out = (float*)d_out;

    float *yp, *hp, *h2p, *scorep, *statsp, *pwnp, *gp;
    int *mapp, *permp, *srcp, *dstp, *validp;
    cudaGetSymbolAddress((void**)&yp, g_y);
    cudaGetSymbolAddress((void**)&hp, g_h);
    cudaGetSymbolAddress((void**)&h2p, g_h2);
    cudaGetSymbolAddress((void**)&scorep, g_score);
    cudaGetSymbolAddress((void**)&statsp, g_stats);
    cudaGetSymbolAddress((void**)&pwnp, g_pwn);
    cudaGetSymbolAddress((void**)&gp, g_gpool);
    cudaGetSymbolAddress((void**)&mapp, g_map);
    cudaGetSymbolAddress((void**)&permp, g_perm);
    cudaGetSymbolAddress((void**)&srcp, g_src);
    cudaGetSymbolAddress((void**)&dstp, g_dst);
    cudaGetSymbolAddress((void**)&validp, g_valid);

    init_edges_k<<<(NE + 255) / 256, 256>>>(ei, srcp, dstp, validp);

    // ---- layer 1: n=4096, cin=64 -> pool to 2048 ----
    gemm_y_k<<<dim3(CED, NN0 / 128), 256>>>(x, nn1_w, nn1_b, yp, NN0, CIN0);
    root_init_k<<<NN0, HH>>>(x, root1, bias1, h2p, CIN0);
    edge_msg_k<<<NE, HH>>>(ea, yp, h2p, srcp, dstp, validp);
    zero_stats_k<<<1, 256>>>(statsp);
    bn_stats_k<<<64, HH>>>(h2p, statsp, NN0);
    pwnorm_k<<<1, HH>>>(pw1, pwnp);
    bn_apply_score_k<<<NN0, HH>>>(h2p, gamma1, beta1, pw1, statsp, pwnp, scorep, NN0);
    topk_k<<<NB, NPG0>>>(scorep, mapp, permp, NPG0, K1);
    gather_k<<<NB * K1, HH>>>(h2p, hp, permp, scorep);
    remap_k<<<(NE + 255) / 256, 256>>>(srcp, dstp, validp, mapp);

    // ---- layer 2: n=2048, cin=128 -> pool to 1024 ----
    int n2 = NB * K1;
    gemm_y_k<<<dim3(CED, n2 / 128), 256>>>(hp, nn2_w, nn2_b, yp, n2, HH);
    root_init_k<<<n2, HH>>>(hp, root2, bias2, h2p, HH);
    edge_msg_k<<<NE, HH>>>(ea, yp, h2p, srcp, dstp, validp);
    zero_stats_k<<<1, 256>>>(statsp);
    bn_stats_k<<<64, HH>>>(h2p, statsp, n2);
    pwnorm_k<<<1, HH>>>(pw2, pwnp);
    bn_apply_score_k<<<n2, HH>>>(h2p, gamma2, beta2, pw2, statsp, pwnp, scorep, n2);
    topk_k<<<NB, K1>>>(scorep, mapp, permp, K1, K2);
    gather_k<<<NB * K2, HH>>>(h2p, hp, permp, scorep);
    remap_k<<<(NE + 255) / 256, 256>>>(srcp, dstp, validp, mapp);

    // ---- layer 3: n=1024, cin=128 -> pool to 512 ----
    int n3 = NB * K2;
    gemm_y_k<<<dim3(CED, n3 / 128), 256>>>(hp, nn3_w, nn3_b, yp, n3, HH);
    root_init_k<<<n3, HH>>>(hp, root3, bias3, h2p, HH);
    edge_msg_k<<<NE, HH>>>(ea, yp, h2p, srcp, dstp, validp);
    zero_stats_k<<<1, 256>>>(statsp);
    bn_stats_k<<<64, HH>>>(h2p, statsp, n3);
    pwnorm_k<<<1, HH>>>(pw3, pwnp);
    bn_apply_score_k<<<n3, HH>>>(h2p, gamma3, beta3, pw3, statsp, pwnp, scorep, n3);
    topk_k<<<NB, K2>>>(scorep, mapp, permp, K2, K3);
    gather_k<<<NB * K3, HH>>>(h2p, hp, permp, scorep);

    // ---- readout ----
    meanpool_k<<<NB, HH>>>(hp, gp);
    mlp_k<<<NB, 64>>>(gp, l1w, l1b, l2w, l2b, out);
}

// round 3
// speedup vs baseline: 1.6603x; 1.6603x over previous
#include <cuda_runtime.h>
#include <cuda_bf16.h>
#include <mma.h>
#include <math.h>
#include <stdint.h>

using namespace nvcuda;

// Problem constants
#define NB   32
#define NPG0 128
#define NE   8192
#define CIN0 64
#define ED   32
#define HH   128
#define CED  33
#define YC   (CED*HH)   // 4224
#define K1   64
#define K2   32
#define K3   16
#define NN0  (NB*NPG0)  // 4096
#define NSPLIT 3        // 3-term bf16 split

// ---------------- scratch (device globals; no allocation) ----------------
__device__ float g_y[NN0 * YC];                          // 69 MB
__device__ __nv_bfloat16 g_Ab[NN0 * NSPLIT * HH];        // split-A [n, 3*cin]
__device__ __nv_bfloat16 g_Bb[YC * NSPLIT * HH];         // split-B^T [4224, 3*cin]
__device__ float g_h[NN0 * HH];
__device__ float g_h2[NN0 * HH];
__device__ float g_score[NN0];
__device__ int   g_map[NN0];
__device__ int   g_perm[NN0];
__device__ int   g_src[NE], g_dst[NE], g_valid[NE];
__device__ float g_stats[2 * HH];
__device__ float g_pwn[1];
__device__ float g_gpool[NB * HH];

// ---------------- split-precision prep ----------------
__device__ __forceinline__ void split2(float x, __nv_bfloat16& h1, __nv_bfloat16& h2) {
    h1 = __float2bfloat16(x);
    float r1 = x - __bfloat162float(h1);
    h2 = __float2bfloat16(r1);
}

// Ab[r, j*cin + k], blocks j: [h1, h1, h2]
__global__ void split_A_k(const float* __restrict__ A, __nv_bfloat16* __restrict__ Ab,
                          int n, int cin) {
    int i = blockIdx.x * blockDim.x + threadIdx.x;
    if (i >= n * cin) return;
    int r = i / cin, k = i - r * cin;
    __nv_bfloat16 h1, h2;
    split2(A[i], h1, h2);
    __nv_bfloat16* row = Ab + (size_t)r * NSPLIT * cin + k;
    row[0] = h1; row[cin] = h1; row[2 * cin] = h2;
}

// BbT[t, j*cin + k], t = d*128+o; source B[k,t] = d<32 ? W[(d*cin+k)*128+o] : bvec[k*128+o]
// blocks j: [b1, b2, b1]   (products: h1*b1 + h1*b2 + h2*b1)
__global__ void split_B_k(const float* __restrict__ W, const float* __restrict__ bvec,
                          __nv_bfloat16* __restrict__ Bb, int cin) {
    int i = blockIdx.x * blockDim.x + threadIdx.x;
    if (i >= YC * cin) return;
    int t = i / cin, k = i - t * cin;
    int d = t >> 7, o = t & 127;
    float w = (d < ED) ? W[(size_t)(d * cin + k) * HH + o] : bvec[(size_t)k * HH + o];
    __nv_bfloat16 b1, b2;
    split2(w, b1, b2);
    __nv_bfloat16* row = Bb + (size_t)t * NSPLIT * cin + k;
    row[0] = b1; row[cin] = b2; row[2 * cin] = b1;
}

// ---------------- WMMA bf16 GEMM: Y[n,4224] = Ab[n,Kp] @ BbT[4224,Kp]^T ----------------
// Block tile 128x128, BK=16, 256 threads (8 warps, 4x2), warp tile 32x64 (2x4 frags).
// All dims divide exactly: n in {4096,2048,1024}, 4224 = 33*128, Kp in {192,384}.
#define BK 16
#define SSTR (BK + 8)   // 24 elems, 48B row stride (16B-aligned for uint4)

__global__ __launch_bounds__(256)
void gemm_wmma_k(const __nv_bfloat16* __restrict__ Ab, const __nv_bfloat16* __restrict__ Bb,
                 float* __restrict__ Y, int Kp) {
    __shared__ __nv_bfloat16 As[128 * SSTR];
    __shared__ __nv_bfloat16 Bs[128 * SSTR];

    const int tid = threadIdx.x;
    const int wid = tid >> 5;
    const int mbase = blockIdx.y * 128;
    const int nbase = blockIdx.x * 128;
    const int warp_m = wid & 3;     // 0..3  -> 32-row slice
    const int warp_n = wid >> 2;    // 0..1  -> 64-col slice

    wmma::fragment<wmma::accumulator, 16, 16, 16, float> acc[2][4];
#pragma unroll
    for (int i = 0; i < 2; i++)
#pragma unroll
        for (int j = 0; j < 4; j++) wmma::fill_fragment(acc[i][j], 0.f);

    // per-thread load mapping: 256 uint4 per tile; row = t>>1, half = t&1
    const int lrow = tid >> 1;
    const int lhalf = tid & 1;
    const __nv_bfloat16* gA = Ab + (size_t)(mbase + lrow) * Kp + lhalf * 8;
    const __nv_bfloat16* gB = Bb + (size_t)(nbase + lrow) * Kp + lhalf * 8;
    __nv_bfloat16* sA = As + lrow * SSTR + lhalf * 8;
    __nv_bfloat16* sB = Bs + lrow * SSTR + lhalf * 8;

    for (int kc = 0; kc < Kp; kc += BK) {
        *reinterpret_cast<uint4*>(sA) = *reinterpret_cast<const uint4*>(gA + kc);
        *reinterpret_cast<uint4*>(sB) = *reinterpret_cast<const uint4*>(gB + kc);
        __syncthreads();

        wmma::fragment<wmma::matrix_a, 16, 16, 16, __nv_bfloat16, wmma::row_major> af[2];
        wmma::fragment<wmma::matrix_b, 16, 16, 16, __nv_bfloat16, wmma::col_major> bf[4];
#pragma unroll
        for (int i = 0; i < 2; i++)
            wmma::load_matrix_sync(af[i], As + (warp_m * 32 + i * 16) * SSTR, SSTR);
#pragma unroll
        for (int j = 0; j < 4; j++)
            wmma::load_matrix_sync(bf[j], Bs + (warp_n * 64 + j * 16) * SSTR, SSTR);
#pragma unroll
        for (int i = 0; i < 2; i++)
#pragma unroll
            for (int j = 0; j < 4; j++)
                wmma::mma_sync(acc[i][j], af[i], bf[j], acc[i][j]);
        __syncthreads();
    }

#pragma unroll
    for (int i = 0; i < 2; i++)
#pragma unroll
        for (int j = 0; j < 4; j++) {
            float* dst = Y + (size_t)(mbase + warp_m * 32 + i * 16) * YC
                           + nbase + warp_n * 64 + j * 16;
            wmma::store_matrix_sync(dst, acc[i][j], YC, wmma::mem_row_major);
        }
}

// ---------------- pipeline kernels (unchanged from R1, which passed) ----------------

__global__ void init_edges_k(const int* __restrict__ ei,
                             int* __restrict__ src, int* __restrict__ dst,
                             int* __restrict__ valid) {
    int e = blockIdx.x * blockDim.x + threadIdx.x;
    if (e < NE) {
        src[e] = ei[e];
        dst[e] = ei[NE + e];
        valid[e] = 1;
    }
}

__global__ void root_init_k(const float* __restrict__ h, const float* __restrict__ root,
                            const float* __restrict__ bias, float* __restrict__ out,
                            int cin) {
    __shared__ float sh[HH];
    int v = blockIdx.x, o = threadIdx.x;
    for (int i = o; i < cin; i += HH) sh[i] = h[(size_t)v * cin + i];
    __syncthreads();
    float acc = bias[o];
    for (int i = 0; i < cin; i++) acc = fmaf(sh[i], root[i * HH + o], acc);
    out[(size_t)v * HH + o] = acc;
}

__global__ void edge_msg_k(const float* __restrict__ ea, const float* __restrict__ y,
                           float* __restrict__ agg,
                           const int* __restrict__ src, const int* __restrict__ dst,
                           const int* __restrict__ valid) {
    int e = blockIdx.x;
    if (!valid[e]) return;
    __shared__ float a[CED];
    int o = threadIdx.x;
    if (o < ED) a[o] = ea[(size_t)e * ED + o];
    if (o == ED) a[ED] = 1.f;
    __syncthreads();
    const float* yr = y + (size_t)src[e] * YC + o;
    float acc = 0.f;
#pragma unroll
    for (int d = 0; d < CED; d++) acc = fmaf(a[d], yr[d * HH], acc);
    atomicAdd(&agg[(size_t)dst[e] * HH + o], acc);
}

__global__ void zero_stats_k(float* __restrict__ stats) {
    int i = threadIdx.x;
    if (i < 2 * HH) stats[i] = 0.f;
}

__global__ void bn_stats_k(const float* __restrict__ h, float* __restrict__ stats, int n) {
    int ch = threadIdx.x;
    float s = 0.f, s2 = 0.f;
    for (int r = blockIdx.x; r < n; r += gridDim.x) {
        float v = h[(size_t)r * HH + ch];
        s += v; s2 += v * v;
    }
    atomicAdd(&stats[ch], s);
    atomicAdd(&stats[HH + ch], s2);
}

__global__ void pwnorm_k(const float* __restrict__ pw, float* __restrict__ pwn) {
    __shared__ float red[HH];
    int i = threadIdx.x;
    float v = pw[i];
    red[i] = v * v;
    __syncthreads();
    for (int st = 64; st > 0; st >>= 1) {
        if (i < st) red[i] += red[i + st];
        __syncthreads();
    }
    if (i == 0) pwn[0] = sqrtf(red[0]);
}

__global__ void bn_apply_score_k(float* __restrict__ h, const float* __restrict__ gamma,
                                 const float* __restrict__ beta, const float* __restrict__ pw,
                                 const float* __restrict__ stats, const float* __restrict__ pwn,
                                 float* __restrict__ score, int n) {
    __shared__ float red[HH];
    int v = blockIdx.x, o = threadIdx.x;
    float inv_n = 1.f / (float)n;
    float mu = stats[o] * inv_n;
    float var = stats[HH + o] * inv_n - mu * mu;
    float val = gamma[o] * (h[(size_t)v * HH + o] - mu) * rsqrtf(var + 1e-5f) + beta[o];
    val = fmaxf(val, 0.f);
    h[(size_t)v * HH + o] = val;
    red[o] = val * pw[o];
    __syncthreads();
    for (int st = 64; st > 0; st >>= 1) {
        if (o < st) red[o] += red[o + st];
        __syncthreads();
    }
    if (o == 0) score[v] = tanhf(red[0] / pwn[0]);
}

__global__ void topk_k(const float* __restrict__ score, int* __restrict__ map,
                       int* __restrict__ perm, int npg, int k) {
    __shared__ float s[NPG0];
    int b = blockIdx.x, i = threadIdx.x;
    int base = b * npg;
    s[i] = score[base + i];
    __syncthreads();
    float mine = s[i];
    int rank = 0;
    for (int j = 0; j < npg; j++) {
        float sj = s[j];
        rank += (sj > mine) || (sj == mine && j < i);
    }
    if (rank < k) {
        int nid = b * k + rank;
        perm[nid] = base + i;
        map[base + i] = nid;
    } else {
        map[base + i] = -1;
    }
}

__global__ void gather_k(const float* __restrict__ hin, float* __restrict__ hout,
                         const int* __restrict__ perm, const float* __restrict__ score) {
    int v = blockIdx.x, o = threadIdx.x;
    int old = perm[v];
    hout[(size_t)v * HH + o] = hin[(size_t)old * HH + o] * score[old];
}

__global__ void remap_k(int* __restrict__ src, int* __restrict__ dst,
                        int* __restrict__ valid, const int* __restrict__ map) {
    int e = blockIdx.x * blockDim.x + threadIdx.x;
    if (e >= NE) return;
    if (valid[e]) {
        int ns = map[src[e]], nd = map[dst[e]];
        if (ns >= 0 && nd >= 0) { src[e] = ns; dst[e] = nd; }
        else valid[e] = 0;
    }
}

__global__ void meanpool_k(const float* __restrict__ h, float* __restrict__ g) {
    int b = blockIdx.x, o = threadIdx.x;
    float acc = 0.f;
#pragma unroll
    for (int i = 0; i < K3; i++) acc += h[(size_t)(b * K3 + i) * HH + o];
    g[b * HH + o] = acc * (1.f / K3);
}

__global__ void mlp_k(const float* __restrict__ g, const float* __restrict__ w1,
                      const float* __restrict__ b1, const float* __restrict__ w2,
                      const float* __restrict__ b2, float* __restrict__ out) {
    __shared__ float sg[HH];
    __shared__ float red[64];
    int b = blockIdx.x, j = threadIdx.x;
    sg[j] = g[b * HH + j];
    sg[j + 64] = g[b * HH + 64 + j];
    __syncthreads();
    float acc = b1[j];
    for (int i = 0; i < HH; i++) acc = fmaf(sg[i], w1[i * 64 + j], acc);
    acc = fmaxf(acc, 0.f);
    red[j] = acc * w2[j];
    __syncthreads();
    for (int st = 32; st > 0; st >>= 1) {
        if (j < st) red[j] += red[j + st];
        __syncthreads();
    }
    if (j == 0) out[b] = 1.f / (1.f + expf(-(red[0] + b2[0])));
}

// ---------------- host ----------------

extern "C" void kernel_launch(void* const* d_in, const int* in_sizes, int n_in,
                              void* d_out, int out_size) {
    const float* x     = (const float*)d_in[0];
    const int*   ei    = (const int*)d_in[1];
    const float* ea    = (const float*)d_in[2];
    const float* nn1_w = (const float*)d_in[4];
    const float* nn1_b = (const float*)d_in[5];
    const float* root1 = (const float*)d_in[6];
    const float* bias1 = (const float*)d_in[7];
    const float* nn2_w = (const float*)d_in[8];
    const float* nn2_b = (const float*)d_in[9];
    const float* root2 = (const float*)d_in[10];
    const float* bias2 = (const float*)d_in[11];
    const float* nn3_w = (const float*)d_in[12];
    const float* nn3_b = (const float*)d_in[13];
    const float* root3 = (const float*)d_in[14];
    const float* bias3 = (const float*)d_in[15];
    const float* gamma1 = (const float*)d_in[16];
    const float* beta1  = (const float*)d_in[17];
    const float* gamma2 = (const float*)d_in[18];
    const float* beta2  = (const float*)d_in[19];
    const float* gamma3 = (const float*)d_in[20];
    const float* beta3  = (const float*)d_in[21];
    const float* pw1 = (const float*)d_in[22];
    const float* pw2 = (const float*)d_in[23];
    const float* pw3 = (const float*)d_in[24];
    const float* l1w = (const float*)d_in[25];
    const float* l1b = (const float*)d_in[26];
    const float* l2w = (const float*)d_in[27];
    const float* l2b = (const float*)d_in[28];
    float* out = (float*)d_out;

    float *yp, *hp, *h2p, *scorep, *statsp, *pwnp, *gp;
    __nv_bfloat16 *Abp, *Bbp;
    int *mapp, *permp, *srcp, *dstp, *validp;
    cudaGetSymbolAddress((void**)&yp, g_y);
    cudaGetSymbolAddress((void**)&Abp, g_Ab);
    cudaGetSymbolAddress((void**)&Bbp, g_Bb);
    cudaGetSymbolAddress((void**)&hp, g_h);
    cudaGetSymbolAddress((void**)&h2p, g_h2);
    cudaGetSymbolAddress((void**)&scorep, g_score);
    cudaGetSymbolAddress((void**)&statsp, g_stats);
    cudaGetSymbolAddress((void**)&pwnp, g_pwn);
    cudaGetSymbolAddress((void**)&gp, g_gpool);
    cudaGetSymbolAddress((void**)&mapp, g_map);
    cudaGetSymbolAddress((void**)&permp, g_perm);
    cudaGetSymbolAddress((void**)&srcp, g_src);
    cudaGetSymbolAddress((void**)&dstp, g_dst);
    cudaGetSymbolAddress((void**)&validp, g_valid);

    init_edges_k<<<(NE + 255) / 256, 256>>>(ei, srcp, dstp, validp);

    // ---- layer 1: n=4096, cin=64, Kp=192 ----
    split_A_k<<<(NN0 * CIN0 + 255) / 256, 256>>>(x, Abp, NN0, CIN0);
    split_B_k<<<(YC * CIN0 + 255) / 256, 256>>>(nn1_w, nn1_b, Bbp, CIN0);
    gemm_wmma_k<<<dim3(CED, NN0 / 128), 256>>>(Abp, Bbp, yp, NSPLIT * CIN0);
    root_init_k<<<NN0, HH>>>(x, root1, bias1, h2p, CIN0);
    edge_msg_k<<<NE, HH>>>(ea, yp, h2p, srcp, dstp, validp);
    zero_stats_k<<<1, 256>>>(statsp);
    bn_stats_k<<<64, HH>>>(h2p, statsp, NN0);
    pwnorm_k<<<1, HH>>>(pw1, pwnp);
    bn_apply_score_k<<<NN0, HH>>>(h2p, gamma1, beta1, pw1, statsp, pwnp, scorep, NN0);
    topk_k<<<NB, NPG0>>>(scorep, mapp, permp, NPG0, K1);
    gather_k<<<NB * K1, HH>>>(h2p, hp, permp, scorep);
    remap_k<<<(NE + 255) / 256, 256>>>(srcp, dstp, validp, mapp);

    // ---- layer 2: n=2048, cin=128, Kp=384 ----
    int n2 = NB * K1;
    split_A_k<<<(n2 * HH + 255) / 256, 256>>>(hp, Abp, n2, HH);
    split_B_k<<<(YC * HH + 255) / 256, 256>>>(nn2_w, nn2_b, Bbp, HH);
    gemm_wmma_k<<<dim3(CED, n2 / 128), 256>>>(Abp, Bbp, yp, NSPLIT * HH);
    root_init_k<<<n2, HH>>>(hp, root2, bias2, h2p, HH);
    edge_msg_k<<<NE, HH>>>(ea, yp, h2p, srcp, dstp, validp);
    zero_stats_k<<<1, 256>>>(statsp);
    bn_stats_k<<<64, HH>>>(h2p, statsp, n2);
    pwnorm_k<<<1, HH>>>(pw2, pwnp);
    bn_apply_score_k<<<n2, HH>>>(h2p, gamma2, beta2, pw2, statsp, pwnp, scorep, n2);
    topk_k<<<NB, K1>>>(scorep, mapp, permp, K1, K2);
    gather_k<<<NB * K2, HH>>>(h2p, hp, permp, scorep);
    remap_k<<<(NE + 255) / 256, 256>>>(srcp, dstp, validp, mapp);

    // ---- layer 3: n=1024, cin=128, Kp=384 ----
    int n3 = NB * K2;
    split_A_k<<<(n3 * HH + 255) / 256, 256>>>(hp, Abp, n3, HH);
    split_B_k<<<(YC * HH + 255) / 256, 256>>>(nn3_w, nn3_b, Bbp, HH);
    gemm_wmma_k<<<dim3(CED, n3 / 128), 256>>>(Abp, Bbp, yp, NSPLIT * HH);
    root_init_k<<<n3, HH>>>(hp, root3, bias3, h2p, HH);
    edge_msg_k<<<NE, HH>>>(ea, yp, h2p, srcp, dstp, validp);
    zero_stats_k<<<1, 256>>>(statsp);
    bn_stats_k<<<64, HH>>>(h2p, statsp, n3);
    pwnorm_k<<<1, HH>>>(pw3, pwnp);
    bn_apply_score_k<<<n3, HH>>>(h2p, gamma3, beta3, pw3, statsp, pwnp, scorep, n3);
    topk_k<<<NB, K2>>>(scorep, mapp, permp, K2, K3);
    gather_k<<<NB * K3, HH>>>(h2p, hp, permp, scorep);

    // ---- readout ----
    meanpool_k<<<NB, HH>>>(hp, gp);
    mlp_k<<<NB, 64>>>(gp, l1w, l1b, l2w, l2b, out);
}

// round 4
// speedup vs baseline: 2.2229x; 1.3389x over previous
#include <cuda_runtime.h>
#include <cuda_bf16.h>
#include <mma.h>
#include <math.h>
#include <stdint.h>

using namespace nvcuda;

// Problem constants
#define NB   32
#define NPG0 128
#define NE   8192
#define EPG  (NE/NB)      // 256 edges per graph (contiguous)
#define CIN0 64
#define ED   32
#define HH   128
#define CED  33           // 32 edge-feature slices + bias slice
#define NDB  34           // + root slice
#define YC2  (NDB*HH)     // 4352
#define K1   64
#define K2   32
#define K3   16
#define NN0  (NB*NPG0)    // 4096
#define NSPLIT 3

// ---------------- scratch ----------------
__device__ float g_y[NN0 * YC2];                      // 71 MB
__device__ __nv_bfloat16 g_Ab[NN0 * NSPLIT * HH];
__device__ __nv_bfloat16 g_Bb[YC2 * NSPLIT * HH];
__device__ float g_h[NN0 * HH];
__device__ float g_h2[NN0 * HH];
__device__ int   g_src[NE], g_dst[NE], g_valid[NE];
__device__ float g_partial[64 * 256];                 // BN partial sums
__device__ float g_gpool[NB * HH];

// ---------------- helpers ----------------
__device__ __forceinline__ void split2(float x, __nv_bfloat16& h1, __nv_bfloat16& h2) {
    h1 = __float2bfloat16(x);
    h2 = __float2bfloat16(x - __bfloat162float(h1));
}
__device__ __forceinline__ uint32_t smem_u32(const void* p) {
    return (uint32_t)__cvta_generic_to_shared(p);
}
__device__ __forceinline__ void cp_async16(uint32_t saddr, const void* gaddr) {
    asm volatile("cp.async.cg.shared.global [%0], [%1], 16;" :: "r"(saddr), "l"(gaddr));
}
__device__ __forceinline__ void cp_commit() {
    asm volatile("cp.async.commit_group;" ::: "memory");
}

// ---------------- split prep ----------------
// Ab[r, j*cin+k], blocks [h1, h1, h2]
__global__ void split_A_k(const float* __restrict__ A, __nv_bfloat16* __restrict__ Ab,
                          int n, int cin) {
    int i = blockIdx.x * blockDim.x + threadIdx.x;
    if (i >= n * cin) return;
    int r = i / cin, k = i - r * cin;
    __nv_bfloat16 h1, h2;
    split2(A[i], h1, h2);
    __nv_bfloat16* row = Ab + (size_t)r * NSPLIT * cin + k;
    row[0] = h1; row[cin] = h1; row[2 * cin] = h2;
}

// BbT[t, j*cin+k], blocks [b1, b2, b1]; t = d*128+o
// d<32: W[(d*cin+k)*128+o]; d==32: bvec[k*128+o]; d==33: root[k*128+o]
__global__ void split_B_k(const float* __restrict__ W, const float* __restrict__ bvec,
                          const float* __restrict__ root, __nv_bfloat16* __restrict__ Bb,
                          int cin) {
    int i = blockIdx.x * blockDim.x + threadIdx.x;
    if (i >= YC2 * cin) return;
    int t = i / cin, k = i - t * cin;
    int d = t >> 7, o = t & 127;
    float w;
    if (d < ED)       w = W[(size_t)(d * cin + k) * HH + o];
    else if (d == ED) w = bvec[(size_t)k * HH + o];
    else              w = root[(size_t)k * HH + o];
    __nv_bfloat16 b1, b2;
    split2(w, b1, b2);
    __nv_bfloat16* row = Bb + (size_t)t * NSPLIT * cin + k;
    row[0] = b1; row[cin] = b2; row[2 * cin] = b1;
}

// ---------------- pipelined WMMA GEMM ----------------
// Y[n, 4352] = Ab[n,Kp] @ BbT[4352,Kp]^T ; block 128x128, BK=32, cp.async 2 stages.
#define BK 32
#define SSTR 40   // element stride (80B, 16B aligned)

__global__ __launch_bounds__(256)
void gemm_wmma_k(const __nv_bfloat16* __restrict__ Ab, const __nv_bfloat16* __restrict__ Bb,
                 float* __restrict__ Y, int Kp) {
    __shared__ __nv_bfloat16 As[2][128 * SSTR];
    __shared__ __nv_bfloat16 Bs[2][128 * SSTR];

    const int tid = threadIdx.x;
    const int wid = tid >> 5;
    const int mbase = blockIdx.y * 128;
    const int nbase = blockIdx.x * 128;
    const int warp_m = wid & 3;
    const int warp_n = wid >> 2;
    const int NC = Kp >> 5;

    wmma::fragment<wmma::accumulator, 16, 16, 16, float> acc[2][4];
#pragma unroll
    for (int i = 0; i < 2; i++)
#pragma unroll
        for (int j = 0; j < 4; j++) wmma::fill_fragment(acc[i][j], 0.f);

    // load mapping: 512 16B-chunks per tile; thread handles chunks tid*2, tid*2+1
    const int r0 = (tid * 2) >> 2, j0 = (tid * 2) & 3;
    const int r1 = (tid * 2 + 1) >> 2, j1 = (tid * 2 + 1) & 3;

    const __nv_bfloat16* gA = Ab + (size_t)mbase * Kp;
    const __nv_bfloat16* gB = Bb + (size_t)nbase * Kp;

    auto prefetch = [&](int c, int s) {
        int kc = c * BK;
        cp_async16(smem_u32(&As[s][r0 * SSTR + j0 * 8]), gA + (size_t)r0 * Kp + kc + j0 * 8);
        cp_async16(smem_u32(&As[s][r1 * SSTR + j1 * 8]), gA + (size_t)r1 * Kp + kc + j1 * 8);
        cp_async16(smem_u32(&Bs[s][r0 * SSTR + j0 * 8]), gB + (size_t)r0 * Kp + kc + j0 * 8);
        cp_async16(smem_u32(&Bs[s][r1 * SSTR + j1 * 8]), gB + (size_t)r1 * Kp + kc + j1 * 8);
        cp_commit();
    };

    prefetch(0, 0);

    for (int c = 0; c < NC; c++) {
        int s = c & 1;
        if (c + 1 < NC) {
            prefetch(c + 1, s ^ 1);
            asm volatile("cp.async.wait_group 1;" ::: "memory");
        } else {
            asm volatile("cp.async.wait_group 0;" ::: "memory");
        }
        __syncthreads();

#pragma unroll
        for (int ks = 0; ks < 2; ks++) {
            wmma::fragment<wmma::matrix_a, 16, 16, 16, __nv_bfloat16, wmma::row_major> af[2];
            wmma::fragment<wmma::matrix_b, 16, 16, 16, __nv_bfloat16, wmma::col_major> bf[4];
#pragma unroll
            for (int i = 0; i < 2; i++)
                wmma::load_matrix_sync(af[i], &As[s][(warp_m * 32 + i * 16) * SSTR + ks * 16], SSTR);
#pragma unroll
            for (int j = 0; j < 4; j++)
                wmma::load_matrix_sync(bf[j], &Bs[s][(warp_n * 64 + j * 16) * SSTR + ks * 16], SSTR);
#pragma unroll
            for (int i = 0; i < 2; i++)
#pragma unroll
                for (int j = 0; j < 4; j++)
                    wmma::mma_sync(acc[i][j], af[i], bf[j], acc[i][j]);
        }
        __syncthreads();
    }

#pragma unroll
    for (int i = 0; i < 2; i++)
#pragma unroll
        for (int j = 0; j < 4; j++) {
            float* dst = Y + (size_t)(mbase + warp_m * 32 + i * 16) * YC2
                           + nbase + warp_n * 64 + j * 16;
            wmma::store_matrix_sync(dst, acc[i][j], YC2, wmma::mem_row_major);
        }
}

// ---------------- pipeline kernels ----------------
__global__ void init_edges_k(const int* __restrict__ ei, int* __restrict__ src,
                             int* __restrict__ dst, int* __restrict__ valid) {
    int e = blockIdx.x * blockDim.x + threadIdx.x;
    if (e < NE) { src[e] = ei[e]; dst[e] = ei[NE + e]; valid[e] = 1; }
}

// h2[v,o] = y[v, 33*128+o] (root term) + bias[o]
__global__ void init_agg_k(const float* __restrict__ y, const float* __restrict__ bias,
                           float* __restrict__ h2) {
    int v = blockIdx.x, o = threadIdx.x;
    h2[(size_t)v * HH + o] = y[(size_t)v * YC2 + 33 * HH + o] + bias[o];
}

__global__ void edge_msg_k(const float* __restrict__ ea, const float* __restrict__ y,
                           float* __restrict__ agg, const int* __restrict__ src,
                           const int* __restrict__ dst, const int* __restrict__ valid) {
    int e = blockIdx.x;
    if (!valid[e]) return;
    __shared__ float a[CED];
    int o = threadIdx.x;
    if (o < ED) a[o] = ea[(size_t)e * ED + o];
    if (o == ED) a[ED] = 1.f;
    __syncthreads();
    const float* yr = y + (size_t)src[e] * YC2 + o;
    float acc = 0.f;
#pragma unroll
    for (int d = 0; d < CED; d++) acc = fmaf(a[d], yr[d * HH], acc);
    atomicAdd(&agg[(size_t)dst[e] * HH + o], acc);
}

// deterministic BN partials: block j sums rows j, j+64, ...
__global__ void bn_stats_k(const float* __restrict__ h, float* __restrict__ partial, int n) {
    int j = blockIdx.x, o = threadIdx.x;
    float s = 0.f, s2 = 0.f;
    for (int r = j; r < n; r += 64) {
        float v = h[(size_t)r * HH + o];
        s += v; s2 += v * v;
    }
    partial[j * 256 + o] = s;
    partial[j * 256 + 128 + o] = s2;
}

// fused: BN apply + ReLU + score + topk + gather(+scale) + split-A + edge remap.
// one block per graph, 128 threads.
__global__ void fused_pool_k(const float* __restrict__ h2, const float* __restrict__ partial,
                             const float* __restrict__ gamma, const float* __restrict__ beta,
                             const float* __restrict__ pw,
                             float* __restrict__ hout, __nv_bfloat16* __restrict__ Ab,
                             int* __restrict__ src, int* __restrict__ dst,
                             int* __restrict__ valid,
                             int npg, int kk, int n) {
    extern __shared__ float fs[];
    float* tile = fs;                       // npg * 129
    float* spw  = tile + npg * 129;         // 128
    float* sc   = spw + 128;                // npg
    float* red  = sc + npg;                 // 128
    int*   rankA = (int*)(red + 128);       // npg

    const int b = blockIdx.x, o = threadIdx.x;
    const int base = b * npg;

    // reduce BN partials
    float s = 0.f, s2 = 0.f;
#pragma unroll 8
    for (int j = 0; j < 64; j++) {
        s  += partial[j * 256 + o];
        s2 += partial[j * 256 + 128 + o];
    }
    float inv_n = 1.f / (float)n;
    float mu = s * inv_n;
    float var = s2 * inv_n - mu * mu;
    float scal = gamma[o] * rsqrtf(var + 1e-5f);
    float be = beta[o];

    float pwo = pw[o];
    spw[o] = pwo;
    red[o] = pwo * pwo;
    __syncthreads();
    for (int st = 64; st > 0; st >>= 1) {
        if (o < st) red[o] += red[o + st];
        __syncthreads();
    }
    float pwn = sqrtf(red[0]);

    // BN + ReLU into smem tile
    for (int i = 0; i < npg; i++) {
        float v = h2[(size_t)(base + i) * HH + o];
        tile[i * 129 + o] = fmaxf(scal * (v - mu) + be, 0.f);
    }
    __syncthreads();

    // scores: thread i = node i
    if (o < npg) {
        float acc = 0.f;
#pragma unroll 16
        for (int c = 0; c < HH; c++) acc += tile[o * 129 + c] * spw[c];
        sc[o] = tanhf(acc / pwn);
    }
    __syncthreads();

    // rank = count of strictly better (index tie-break)
    if (o < npg) {
        float mine = sc[o];
        int r = 0;
        for (int j = 0; j < npg; j++) {
            float sj = sc[j];
            r += (sj > mine) || (sj == mine && j < o);
        }
        rankA[o] = r;
    }
    __syncthreads();

    // gather kept nodes: hout + split-A (cin=128 next layer)
    for (int i = 0; i < npg; i++) {
        int r = rankA[i];
        if (r < kk) {
            int nid = b * kk + r;
            float val = tile[i * 129 + o] * sc[i];
            hout[(size_t)nid * HH + o] = val;
            __nv_bfloat16 h1, h2b;
            split2(val, h1, h2b);
            __nv_bfloat16* row = Ab + (size_t)nid * (NSPLIT * HH) + o;
            row[0] = h1; row[HH] = h1; row[2 * HH] = h2b;
        }
    }

    // remap this graph's edges
    for (int e = b * EPG + o; e < (b + 1) * EPG; e += 128) {
        if (valid[e]) {
            int rs = rankA[src[e] - base];
            int rd = rankA[dst[e] - base];
            if (rs < kk && rd < kk) { src[e] = b * kk + rs; dst[e] = b * kk + rd; }
            else valid[e] = 0;
        }
    }
}

__global__ void meanpool_k(const float* __restrict__ h, float* __restrict__ g) {
    int b = blockIdx.x, o = threadIdx.x;
    float acc = 0.f;
#pragma unroll
    for (int i = 0; i < K3; i++) acc += h[(size_t)(b * K3 + i) * HH + o];
    g[b * HH + o] = acc * (1.f / K3);
}

__global__ void mlp_k(const float* __restrict__ g, const float* __restrict__ w1,
                      const float* __restrict__ b1, const float* __restrict__ w2,
                      const float* __restrict__ b2, float* __restrict__ out) {
    __shared__ float sg[HH];
    __shared__ float red[64];
    int b = blockIdx.x, j = threadIdx.x;
    sg[j] = g[b * HH + j];
    sg[j + 64] = g[b * HH + 64 + j];
    __syncthreads();
    float acc = b1[j];
    for (int i = 0; i < HH; i++) acc = fmaf(sg[i], w1[i * 64 + j], acc);
    acc = fmaxf(acc, 0.f);
    red[j] = acc * w2[j];
    __syncthreads();
    for (int st = 32; st > 0; st >>= 1) {
        if (j < st) red[j] += red[j + st];
        __syncthreads();
    }
    if (j == 0) out[b] = 1.f / (1.f + expf(-(red[0] + b2[0])));
}

// ---------------- host ----------------
extern "C" void kernel_launch(void* const* d_in, const int* in_sizes, int n_in,
                              void* d_out, int out_size) {
    const float* x     = (const float*)d_in[0];
    const int*   ei    = (const int*)d_in[1];
    const float* ea    = (const float*)d_in[2];
    const float* nn1_w = (const float*)d_in[4];
    const float* nn1_b = (const float*)d_in[5];
    const float* root1 = (const float*)d_in[6];
    const float* bias1 = (const float*)d_in[7];
    const float* nn2_w = (const float*)d_in[8];
    const float* nn2_b = (const float*)d_in[9];
    const float* root2 = (const float*)d_in[10];
    const float* bias2 = (const float*)d_in[11];
    const float* nn3_w = (const float*)d_in[12];
    const float* nn3_b = (const float*)d_in[13];
    const float* root3 = (const float*)d_in[14];
    const float* bias3 = (const float*)d_in[15];
    const float* gamma1 = (const float*)d_in[16];
    const float* beta1  = (const float*)d_in[17];
    const float* gamma2 = (const float*)d_in[18];
    const float* beta2  = (const float*)d_in[19];
    const float* gamma3 = (const float*)d_in[20];
    const float* beta3  = (const float*)d_in[21];
    const float* pw1 = (const float*)d_in[22];
    const float* pw2 = (const float*)d_in[23];
    const float* pw3 = (const float*)d_in[24];
    const float* l1w = (const float*)d_in[25];
    const float* l1b = (const float*)d_in[26];
    const float* l2w = (const float*)d_in[27];
    const float* l2b = (const float*)d_in[28];
    float* out = (float*)d_out;

    float *yp, *hp, *h2p, *partp, *gp;
    __nv_bfloat16 *Abp, *Bbp;
    int *srcp, *dstp, *validp;
    cudaGetSymbolAddress((void**)&yp, g_y);
    cudaGetSymbolAddress((void**)&Abp, g_Ab);
    cudaGetSymbolAddress((void**)&Bbp, g_Bb);
    cudaGetSymbolAddress((void**)&hp, g_h);
    cudaGetSymbolAddress((void**)&h2p, g_h2);
    cudaGetSymbolAddress((void**)&partp, g_partial);
    cudaGetSymbolAddress((void**)&gp, g_gpool);
    cudaGetSymbolAddress((void**)&srcp, g_src);
    cudaGetSymbolAddress((void**)&dstp, g_dst);
    cudaGetSymbolAddress((void**)&validp, g_valid);

    const int POOL_SMEM = (NPG0 * 129 + 128 + NPG0 + 128 + NPG0) * 4;
    cudaFuncSetAttribute(fused_pool_k, cudaFuncAttributeMaxDynamicSharedMemorySize, POOL_SMEM);

    init_edges_k<<<(NE + 255) / 256, 256>>>(ei, srcp, dstp, validp);

    // ---- layer 1: n=4096, cin=64, Kp=192 ----
    split_A_k<<<(NN0 * CIN0 + 255) / 256, 256>>>(x, Abp, NN0, CIN0);
    split_B_k<<<(YC2 * CIN0 + 255) / 256, 256>>>(nn1_w, nn1_b, root1, Bbp, CIN0);
    gemm_wmma_k<<<dim3(NDB, NN0 / 128), 256>>>(Abp, Bbp, yp, NSPLIT * CIN0);
    init_agg_k<<<NN0, HH>>>(yp, bias1, h2p);
    edge_msg_k<<<NE, HH>>>(ea, yp, h2p, srcp, dstp, validp);
    bn_stats_k<<<64, HH>>>(h2p, partp, NN0);
    fused_pool_k<<<NB, HH, (NPG0 * 129 + 128 + 2 * NPG0 + 128) * 4>>>(
        h2p, partp, gamma1, beta1, pw1, hp, Abp, srcp, dstp, validp, NPG0, K1, NN0);

    // ---- layer 2: n=2048, cin=128, Kp=384 ----
    int n2 = NB * K1;
    split_B_k<<<(YC2 * HH + 255) / 256, 256>>>(nn2_w, nn2_b, root2, Bbp, HH);
    gemm_wmma_k<<<dim3(NDB, n2 / 128), 256>>>(Abp, Bbp, yp, NSPLIT * HH);
    init_agg_k<<<n2, HH>>>(yp, bias2, h2p);
    edge_msg_k<<<NE, HH>>>(ea, yp, h2p, srcp, dstp, validp);
    bn_stats_k<<<64, HH>>>(h2p, partp, n2);
    fused_pool_k<<<NB, HH, (K1 * 129 + 128 + 2 * K1 + 128) * 4>>>(
        h2p, partp, gamma2, beta2, pw2, hp, Abp, srcp, dstp, validp, K1, K2, n2);

    // ---- layer 3: n=1024, cin=128, Kp=384 ----
    int n3 = NB * K2;
    split_B_k<<<(YC2 * HH + 255) / 256, 256>>>(nn3_w, nn3_b, root3, Bbp, HH);
    gemm_wmma_k<<<dim3(NDB, n3 / 128), 256>>>(Abp, Bbp, yp, NSPLIT * HH);
    init_agg_k<<<n3, HH>>>(yp, bias3, h2p);
    edge_msg_k<<<NE, HH>>>(ea, yp, h2p, srcp, dstp, validp);
    bn_stats_k<<<64, HH>>>(h2p, partp, n3);
    fused_pool_k<<<NB, HH, (K2 * 129 + 128 + 2 * K2 + 128) * 4>>>(
        h2p, partp, gamma3, beta3, pw3, hp, Abp, srcp, dstp, validp, K2, K3, n3);

    // ---- readout ----
    meanpool_k<<<NB, HH>>>(hp, gp);
    mlp_k<<<NB, 64>>>(gp, l1w, l1b, l2w, l2b, out);
}

// round 5
// speedup vs baseline: 2.4871x; 1.1188x over previous
#include <cuda_runtime.h>
#include <cuda_bf16.h>
#include <math.h>
#include <stdint.h>

// Problem constants
#define NB   32
#define NPG0 128
#define NE   8192
#define EPG  (NE/NB)      // 256 edges per graph (contiguous)
#define CIN0 64
#define ED   32
#define HH   128
#define CED  33           // 32 edge-feature slices + bias slice
#define NDB  34           // + root slice (diverted to h2 in epilogue)
#define YC   (CED*HH)     // 4224 (Y stride; root slice not stored)
#define K1   64
#define K2   32
#define K3   16
#define NN0  (NB*NPG0)    // 4096
#define NSPLIT 3

// ---------------- scratch ----------------
__device__ float g_y[NN0 * YC];                       // 69 MB
__device__ __nv_bfloat16 g_Ab[NN0 * NSPLIT * HH];
__device__ __nv_bfloat16 g_Bb[(NDB * HH) * NSPLIT * HH];
__device__ float g_h[NN0 * HH];
__device__ float g_h2[NN0 * HH];
__device__ int   g_src[NE], g_dst[NE], g_valid[NE];
__device__ float g_partial[64 * 256];
__device__ float g_gpool[NB * HH];

// ---------------- helpers ----------------
__device__ __forceinline__ void split2(float x, __nv_bfloat16& h1, __nv_bfloat16& h2) {
    h1 = __float2bfloat16(x);
    h2 = __float2bfloat16(x - __bfloat162float(h1));
}
__device__ __forceinline__ uint32_t smem_u32(const void* p) {
    return (uint32_t)__cvta_generic_to_shared(p);
}
__device__ __forceinline__ void cp_async16(uint32_t saddr, const void* gaddr) {
    asm volatile("cp.async.cg.shared.global [%0], [%1], 16;" :: "r"(saddr), "l"(gaddr));
}
__device__ __forceinline__ void ldsm4(uint32_t& r0, uint32_t& r1, uint32_t& r2, uint32_t& r3,
                                      uint32_t addr) {
    asm volatile("ldmatrix.sync.aligned.m8n8.x4.shared.b16 {%0,%1,%2,%3}, [%4];"
                 : "=r"(r0), "=r"(r1), "=r"(r2), "=r"(r3) : "r"(addr));
}
__device__ __forceinline__ void mma16816(float* c, const uint32_t* a, const uint32_t* b) {
    asm volatile("mma.sync.aligned.m16n8k16.row.col.f32.bf16.bf16.f32 "
                 "{%0,%1,%2,%3}, {%4,%5,%6,%7}, {%8,%9}, {%0,%1,%2,%3};"
                 : "+f"(c[0]), "+f"(c[1]), "+f"(c[2]), "+f"(c[3])
                 : "r"(a[0]), "r"(a[1]), "r"(a[2]), "r"(a[3]), "r"(b[0]), "r"(b[1]));
}

// ---------------- split prep ----------------
// Ab[r, j*cin+k], blocks [h1, h1, h2]
__global__ void split_A_k(const float* __restrict__ A, __nv_bfloat16* __restrict__ Ab,
                          int n, int cin) {
    int i = blockIdx.x * blockDim.x + threadIdx.x;
    if (i >= n * cin) return;
    int r = i / cin, k = i - r * cin;
    __nv_bfloat16 h1, h2;
    split2(A[i], h1, h2);
    __nv_bfloat16* row = Ab + (size_t)r * NSPLIT * cin + k;
    row[0] = h1; row[cin] = h1; row[2 * cin] = h2;
}

// BbT[t, j*cin+k], blocks [b1, b2, b1]; t = d*128+o
__global__ void split_B_k(const float* __restrict__ W, const float* __restrict__ bvec,
                          const float* __restrict__ root, __nv_bfloat16* __restrict__ Bb,
                          int cin) {
    int i = blockIdx.x * blockDim.x + threadIdx.x;
    if (i >= NDB * HH * cin) return;
    int t = i / cin, k = i - t * cin;
    int d = t >> 7, o = t & 127;
    float w;
    if (d < ED)       w = W[(size_t)(d * cin + k) * HH + o];
    else if (d == ED) w = bvec[(size_t)k * HH + o];
    else              w = root[(size_t)k * HH + o];
    __nv_bfloat16 b1, b2;
    split2(w, b1, b2);
    __nv_bfloat16* row = Bb + (size_t)t * NSPLIT * cin + k;
    row[0] = b1; row[cin] = b2; row[2 * cin] = b1;
}

// ---------------- raw mma.sync GEMM ----------------
// C[128,128] per block; 8 warps (4 m x 2 n), warp tile 32x64; BK=32; 3-stage cp.async.
// Block x == 33 computes the root slice -> h2 = acc + bias (init_agg fused).
#define SROW 40                // bf16 elems per smem row slot (80B): conflict-free ldmatrix
#define STG (128 * SROW)       // elems per matrix per stage
#define GEMM_SMEM (3 * 2 * STG * 2)   // bytes = 61440

__global__ __launch_bounds__(256, 2)
void gemm_mma_k(const __nv_bfloat16* __restrict__ Ab, const __nv_bfloat16* __restrict__ Bb,
                float* __restrict__ Y, const float* __restrict__ bias,
                float* __restrict__ h2, int Kp) {
    extern __shared__ __nv_bfloat16 sm[];
    const int tid = threadIdx.x;
    const int lane = tid & 31;
    const int wid = tid >> 5;
    const int warp_m = wid & 3;
    const int warp_n = wid >> 2;
    const int mbase = blockIdx.y * 128;
    const int nbase = blockIdx.x * 128;
    const int NC = Kp >> 5;

    float acc[2][8][4];
#pragma unroll
    for (int i = 0; i < 2; i++)
#pragma unroll
        for (int j = 0; j < 8; j++)
#pragma unroll
            for (int q = 0; q < 4; q++) acc[i][j][q] = 0.f;

    // prefetch one BK=32 tile-pair into stage s
    auto prefetch = [&](int cIdx, int s) {
        const int kc = cIdx * 32;
        __nv_bfloat16* base = sm + s * 2 * STG;
#pragma unroll
        for (int u = 0; u < 4; u++) {
            int q = tid + u * 256;          // 0..1023
            int isB = q >> 9;
            int qq = q & 511;
            int r = qq >> 2, ch = qq & 3;
            const __nv_bfloat16* g = isB
                ? (Bb + (size_t)(nbase + r) * Kp + kc + ch * 8)
                : (Ab + (size_t)(mbase + r) * Kp + kc + ch * 8);
            cp_async16(smem_u32(base + isB * STG + r * SROW + ch * 8), g);
        }
        asm volatile("cp.async.commit_group;" ::: "memory");
    };

    prefetch(0, 0);
    prefetch(1, 1);
    prefetch(2, 2);

    for (int c = 0; c < NC; c++) {
        int pend = NC - 1 - c; if (pend > 2) pend = 2;
        if (pend == 2)      asm volatile("cp.async.wait_group 2;" ::: "memory");
        else if (pend == 1) asm volatile("cp.async.wait_group 1;" ::: "memory");
        else                asm volatile("cp.async.wait_group 0;" ::: "memory");
        __syncthreads();

        const int s = c % 3;
        const uint32_t a_base = smem_u32(sm + s * 2 * STG);
        const uint32_t b_base = a_base + STG * 2;   // bytes

#pragma unroll
        for (int kk = 0; kk < 2; kk++) {
            uint32_t a[2][4];
#pragma unroll
            for (int i = 0; i < 2; i++) {
                int arow = warp_m * 32 + i * 16 + (lane & 15);
                int acol = kk * 16 + (lane >> 4) * 8;
                ldsm4(a[i][0], a[i][1], a[i][2], a[i][3],
                      a_base + (uint32_t)(arow * SROW + acol) * 2);
            }
            uint32_t b[8][2];
#pragma unroll
            for (int g = 0; g < 4; g++) {
                int m8 = lane >> 3;          // 0..3
                int nrow = warp_n * 64 + (2 * g + (m8 >> 1)) * 8 + (lane & 7);
                int kcol = kk * 16 + (m8 & 1) * 8;
                ldsm4(b[2 * g][0], b[2 * g][1], b[2 * g + 1][0], b[2 * g + 1][1],
                      b_base + (uint32_t)(nrow * SROW + kcol) * 2);
            }
#pragma unroll
            for (int i = 0; i < 2; i++)
#pragma unroll
                for (int j = 0; j < 8; j++)
                    mma16816(acc[i][j], a[i], b[j]);
        }
        __syncthreads();
        if (c + 3 < NC) prefetch(c + 3, s);
    }

    // epilogue: c-frag: {c0,c1}=C[gid][tig*2..+1], {c2,c3}=C[gid+8][tig*2..+1]
    const int gid = lane >> 2, tig = lane & 3;
    if (blockIdx.x == 33) {
#pragma unroll
        for (int i = 0; i < 2; i++) {
            int row = mbase + warp_m * 32 + i * 16 + gid;
#pragma unroll
            for (int j = 0; j < 8; j++) {
                int col = warp_n * 64 + j * 8 + tig * 2;
                float b0 = bias[col], b1 = bias[col + 1];
                float* d0 = h2 + (size_t)row * HH + col;
                d0[0] = acc[i][j][0] + b0;
                d0[1] = acc[i][j][1] + b1;
                float* d1 = h2 + (size_t)(row + 8) * HH + col;
                d1[0] = acc[i][j][2] + b0;
                d1[1] = acc[i][j][3] + b1;
            }
        }
    } else {
#pragma unroll
        for (int i = 0; i < 2; i++) {
            int row = mbase + warp_m * 32 + i * 16 + gid;
#pragma unroll
            for (int j = 0; j < 8; j++) {
                int col = nbase + warp_n * 64 + j * 8 + tig * 2;
                *reinterpret_cast<float2*>(Y + (size_t)row * YC + col) =
                    make_float2(acc[i][j][0], acc[i][j][1]);
                *reinterpret_cast<float2*>(Y + (size_t)(row + 8) * YC + col) =
                    make_float2(acc[i][j][2], acc[i][j][3]);
            }
        }
    }
}

// ---------------- pipeline kernels ----------------
__global__ void init_edges_k(const int* __restrict__ ei, int* __restrict__ src,
                             int* __restrict__ dst, int* __restrict__ valid) {
    int e = blockIdx.x * blockDim.x + threadIdx.x;
    if (e < NE) { src[e] = ei[e]; dst[e] = ei[NE + e]; valid[e] = 1; }
}

__global__ void edge_msg_k(const float* __restrict__ ea, const float* __restrict__ y,
                           float* __restrict__ agg, const int* __restrict__ src,
                           const int* __restrict__ dst, const int* __restrict__ valid) {
    int e = blockIdx.x;
    if (!valid[e]) return;
    __shared__ float a[CED];
    int o = threadIdx.x;
    if (o < ED) a[o] = ea[(size_t)e * ED + o];
    if (o == ED) a[ED] = 1.f;
    __syncthreads();
    const float* yr = y + (size_t)src[e] * YC + o;
    float acc = 0.f;
#pragma unroll
    for (int d = 0; d < CED; d++) acc = fmaf(a[d], yr[d * HH], acc);
    atomicAdd(&agg[(size_t)dst[e] * HH + o], acc);
}

// deterministic BN partials: block j sums rows j, j+64, ...
__global__ void bn_stats_k(const float* __restrict__ h, float* __restrict__ partial, int n) {
    int j = blockIdx.x, o = threadIdx.x;
    float s = 0.f, s2 = 0.f;
    for (int r = j; r < n; r += 64) {
        float v = h[(size_t)r * HH + o];
        s += v; s2 += v * v;
    }
    partial[j * 256 + o] = s;
    partial[j * 256 + 128 + o] = s2;
}

// fused: BN apply + ReLU + score + topk + gather(+scale) + split-A + edge remap.
__global__ void fused_pool_k(const float* __restrict__ h2, const float* __restrict__ partial,
                             const float* __restrict__ gamma, const float* __restrict__ beta,
                             const float* __restrict__ pw,
                             float* __restrict__ hout, __nv_bfloat16* __restrict__ Ab,
                             int* __restrict__ src, int* __restrict__ dst,
                             int* __restrict__ valid,
                             int npg, int kk, int n) {
    extern __shared__ float fs[];
    float* tile = fs;                       // npg * 129
    float* spw  = tile + npg * 129;         // 128
    float* sc   = spw + 128;                // npg
    float* red  = sc + npg;                 // 128
    int*   rankA = (int*)(red + 128);       // npg

    const int b = blockIdx.x, o = threadIdx.x;
    const int base = b * npg;

    float s = 0.f, s2 = 0.f;
#pragma unroll 8
    for (int j = 0; j < 64; j++) {
        s  += partial[j * 256 + o];
        s2 += partial[j * 256 + 128 + o];
    }
    float inv_n = 1.f / (float)n;
    float mu = s * inv_n;
    float var = s2 * inv_n - mu * mu;
    float scal = gamma[o] * rsqrtf(var + 1e-5f);
    float be = beta[o];

    float pwo = pw[o];
    spw[o] = pwo;
    red[o] = pwo * pwo;
    __syncthreads();
    for (int st = 64; st > 0; st >>= 1) {
        if (o < st) red[o] += red[o + st];
        __syncthreads();
    }
    float pwn = sqrtf(red[0]);

    for (int i = 0; i < npg; i++) {
        float v = h2[(size_t)(base + i) * HH + o];
        tile[i * 129 + o] = fmaxf(scal * (v - mu) + be, 0.f);
    }
    __syncthreads();

    if (o < npg) {
        float acc = 0.f;
#pragma unroll 16
        for (int c = 0; c < HH; c++) acc += tile[o * 129 + c] * spw[c];
        sc[o] = tanhf(acc / pwn);
    }
    __syncthreads();

    if (o < npg) {
        float mine = sc[o];
        int r = 0;
        for (int j = 0; j < npg; j++) {
            float sj = sc[j];
            r += (sj > mine) || (sj == mine && j < o);
        }
        rankA[o] = r;
    }
    __syncthreads();

    for (int i = 0; i < npg; i++) {
        int r = rankA[i];
        if (r < kk) {
            int nid = b * kk + r;
            float val = tile[i * 129 + o] * sc[i];
            hout[(size_t)nid * HH + o] = val;
            __nv_bfloat16 h1, h2b;
            split2(val, h1, h2b);
            __nv_bfloat16* row = Ab + (size_t)nid * (NSPLIT * HH) + o;
            row[0] = h1; row[HH] = h1; row[2 * HH] = h2b;
        }
    }

    for (int e = b * EPG + o; e < (b + 1) * EPG; e += 128) {
        if (valid[e]) {
            int rs = rankA[src[e] - base];
            int rd = rankA[dst[e] - base];
            if (rs < kk && rd < kk) { src[e] = b * kk + rs; dst[e] = b * kk + rd; }
            else valid[e] = 0;
        }
    }
}

__global__ void meanpool_k(const float* __restrict__ h, float* __restrict__ g) {
    int b = blockIdx.x, o = threadIdx.x;
    float acc = 0.f;
#pragma unroll
    for (int i = 0; i < K3; i++) acc += h[(size_t)(b * K3 + i) * HH + o];
    g[b * HH + o] = acc * (1.f / K3);
}

__global__ void mlp_k(const float* __restrict__ g, const float* __restrict__ w1,
                      const float* __restrict__ b1, const float* __restrict__ w2,
                      const float* __restrict__ b2, float* __restrict__ out) {
    __shared__ float sg[HH];
    __shared__ float red[64];
    int b = blockIdx.x, j = threadIdx.x;
    sg[j] = g[b * HH + j];
    sg[j + 64] = g[b * HH + 64 + j];
    __syncthreads();
    float acc = b1[j];
    for (int i = 0; i < HH; i++) acc = fmaf(sg[i], w1[i * 64 + j], acc);
    acc = fmaxf(acc, 0.f);
    red[j] = acc * w2[j];
    __syncthreads();
    for (int st = 32; st > 0; st >>= 1) {
        if (j < st) red[j] += red[j + st];
        __syncthreads();
    }
    if (j == 0) out[b] = 1.f / (1.f + expf(-(red[0] + b2[0])));
}

// ---------------- host ----------------
extern "C" void kernel_launch(void* const* d_in, const int* in_sizes, int n_in,
                              void* d_out, int out_size) {
    const float* x     = (const float*)d_in[0];
    const int*   ei    = (const int*)d_in[1];
    const float* ea    = (const float*)d_in[2];
    const float* nn1_w = (const float*)d_in[4];
    const float* nn1_b = (const float*)d_in[5];
    const float* root1 = (const float*)d_in[6];
    const float* bias1 = (const float*)d_in[7];
    const float* nn2_w = (const float*)d_in[8];
    const float* nn2_b = (const float*)d_in[9];
    const float* root2 = (const float*)d_in[10];
    const float* bias2 = (const float*)d_in[11];
    const float* nn3_w = (const float*)d_in[12];
    const float* nn3_b = (const float*)d_in[13];
    const float* root3 = (const float*)d_in[14];
    const float* bias3 = (const float*)d_in[15];
    const float* gamma1 = (const float*)d_in[16];
    const float* beta1  = (const float*)d_in[17];
    const float* gamma2 = (const float*)d_in[18];
    const float* beta2  = (const float*)d_in[19];
    const float* gamma3 = (const float*)d_in[20];
    const float* beta3  = (const float*)d_in[21];
    const float* pw1 = (const float*)d_in[22];
    const float* pw2 = (const float*)d_in[23];
    const float* pw3 = (const float*)d_in[24];
    const float* l1w = (const float*)d_in[25];
    const float* l1b = (const float*)d_in[26];
    const float* l2w = (const float*)d_in[27];
    const float* l2b = (const float*)d_in[28];
    float* out = (float*)d_out;

    float *yp, *hp, *h2p, *partp, *gp;
    __nv_bfloat16 *Abp, *Bbp;
    int *srcp, *dstp, *validp;
    cudaGetSymbolAddress((void**)&yp, g_y);
    cudaGetSymbolAddress((void**)&Abp, g_Ab);
    cudaGetSymbolAddress((void**)&Bbp, g_Bb);
    cudaGetSymbolAddress((void**)&hp, g_h);
    cudaGetSymbolAddress((void**)&h2p, g_h2);
    cudaGetSymbolAddress((void**)&partp, g_partial);
    cudaGetSymbolAddress((void**)&gp, g_gpool);
    cudaGetSymbolAddress((void**)&srcp, g_src);
    cudaGetSymbolAddress((void**)&dstp, g_dst);
    cudaGetSymbolAddress((void**)&validp, g_valid);

    cudaFuncSetAttribute(gemm_mma_k, cudaFuncAttributeMaxDynamicSharedMemorySize, GEMM_SMEM);
    const int POOL_SMEM = (NPG0 * 129 + 128 + 2 * NPG0 + 128) * 4;
    cudaFuncSetAttribute(fused_pool_k, cudaFuncAttributeMaxDynamicSharedMemorySize, POOL_SMEM);

    init_edges_k<<<(NE + 255) / 256, 256>>>(ei, srcp, dstp, validp);

    // ---- layer 1: n=4096, cin=64, Kp=192 ----
    split_A_k<<<(NN0 * CIN0 + 255) / 256, 256>>>(x, Abp, NN0, CIN0);
    split_B_k<<<(NDB * HH * CIN0 + 255) / 256, 256>>>(nn1_w, nn1_b, root1, Bbp, CIN0);
    gemm_mma_k<<<dim3(NDB, NN0 / 128), 256, GEMM_SMEM>>>(Abp, Bbp, yp, bias1, h2p,
                                                         NSPLIT * CIN0);
    edge_msg_k<<<NE, HH>>>(ea, yp, h2p, srcp, dstp, validp);
    bn_stats_k<<<64, HH>>>(h2p, partp, NN0);
    fused_pool_k<<<NB, HH, (NPG0 * 129 + 128 + 2 * NPG0 + 128) * 4>>>(
        h2p, partp, gamma1, beta1, pw1, hp, Abp, srcp, dstp, validp, NPG0, K1, NN0);

    // ---- layer 2: n=2048, cin=128, Kp=384 ----
    int n2 = NB * K1;
    split_B_k<<<(NDB * HH * HH + 255) / 256, 256>>>(nn2_w, nn2_b, root2, Bbp, HH);
    gemm_mma_k<<<dim3(NDB, n2 / 128), 256, GEMM_SMEM>>>(Abp, Bbp, yp, bias2, h2p,
                                                        NSPLIT * HH);
    edge_msg_k<<<NE, HH>>>(ea, yp, h2p, srcp, dstp, validp);
    bn_stats_k<<<64, HH>>>(h2p, partp, n2);
    fused_pool_k<<<NB, HH, (K1 * 129 + 128 + 2 * K1 + 128) * 4>>>(
        h2p, partp, gamma2, beta2, pw2, hp, Abp, srcp, dstp, validp, K1, K2, n2);

    // ---- layer 3: n=1024, cin=128, Kp=384 ----
    int n3 = NB * K2;
    split_B_k<<<(NDB * HH * HH + 255) / 256, 256>>>(nn3_w, nn3_b, root3, Bbp, HH);
    gemm_mma_k<<<dim3(NDB, n3 / 128), 256, GEMM_SMEM>>>(Abp, Bbp, yp, bias3, h2p,
                                                        NSPLIT * HH);
    edge_msg_k<<<NE, HH>>>(ea, yp, h2p, srcp, dstp, validp);
    bn_stats_k<<<64, HH>>>(h2p, partp, n3);
    fused_pool_k<<<NB, HH, (K2 * 129 + 128 + 2 * K2 + 128) * 4>>>(
        h2p, partp, gamma3, beta3, pw3, hp, Abp, srcp, dstp, validp, K2, K3, n3);

    // ---- readout ----
    meanpool_k<<<NB, HH>>>(hp, gp);
    mlp_k<<<NB, 64>>>(gp, l1w, l1b, l2w, l2b, out);
}

// round 6
// speedup vs baseline: 2.5673x; 1.0323x over previous
#include <cuda_runtime.h>
#include <cuda_bf16.h>
#include <math.h>
#include <stdint.h>

// Problem constants
#define NB   32
#define NPG0 128
#define NE   8192
#define EPG  (NE/NB)      // 256 edges per graph (contiguous)
#define CIN0 64
#define ED   32
#define HH   128
#define CED  33           // 32 edge-feature slices + bias slice
#define NDB  34           // + root slice (diverted to h2 in epilogue)
#define YC   (CED*HH)     // 4224 (Y stride; root slice not stored)
#define K1   64
#define K2   32
#define K3   16
#define NN0  (NB*NPG0)    // 4096
#define NSPLIT 3

// ---------------- scratch ----------------
__device__ float g_y[NN0 * YC];                       // 69 MB
__device__ __nv_bfloat16 g_Ab[NN0 * NSPLIT * HH];
__device__ __nv_bfloat16 g_Bb[(NDB * HH) * NSPLIT * HH];
__device__ float g_h[NN0 * HH];
__device__ float g_h2[NN0 * HH];
__device__ int   g_src[NE], g_dst[NE], g_valid[NE];
__device__ float g_partial[64 * 256];
__device__ float g_gpool[NB * HH];

// ---------------- helpers ----------------
__device__ __forceinline__ void split2(float x, __nv_bfloat16& h1, __nv_bfloat16& h2) {
    h1 = __float2bfloat16(x);
    h2 = __float2bfloat16(x - __bfloat162float(h1));
}
__device__ __forceinline__ uint32_t smem_u32(const void* p) {
    return (uint32_t)__cvta_generic_to_shared(p);
}
__device__ __forceinline__ void cp_async16(uint32_t saddr, const void* gaddr) {
    asm volatile("cp.async.cg.shared.global [%0], [%1], 16;" :: "r"(saddr), "l"(gaddr));
}
__device__ __forceinline__ void ldsm4(uint32_t& r0, uint32_t& r1, uint32_t& r2, uint32_t& r3,
                                      uint32_t addr) {
    asm volatile("ldmatrix.sync.aligned.m8n8.x4.shared.b16 {%0,%1,%2,%3}, [%4];"
                 : "=r"(r0), "=r"(r1), "=r"(r2), "=r"(r3) : "r"(addr));
}
__device__ __forceinline__ void mma16816(float* c, const uint32_t* a, const uint32_t* b) {
    asm volatile("mma.sync.aligned.m16n8k16.row.col.f32.bf16.bf16.f32 "
                 "{%0,%1,%2,%3}, {%4,%5,%6,%7}, {%8,%9}, {%0,%1,%2,%3};"
                 : "+f"(c[0]), "+f"(c[1]), "+f"(c[2]), "+f"(c[3])
                 : "r"(a[0]), "r"(a[1]), "r"(a[2]), "r"(a[3]), "r"(b[0]), "r"(b[1]));
}

// ---------------- split prep ----------------
// Ab[r, j*cin+k], blocks [h1, h1, h2]
__global__ void split_A_k(const float* __restrict__ A, __nv_bfloat16* __restrict__ Ab,
                          int n, int cin) {
    int i = blockIdx.x * blockDim.x + threadIdx.x;
    if (i >= n * cin) return;
    int r = i / cin, k = i - r * cin;
    __nv_bfloat16 h1, h2;
    split2(A[i], h1, h2);
    __nv_bfloat16* row = Ab + (size_t)r * NSPLIT * cin + k;
    row[0] = h1; row[cin] = h1; row[2 * cin] = h2;
}

// BbT[t, j*cin+k], blocks [b1, b2, b1]; t = d*128+o
__global__ void split_B_k(const float* __restrict__ W, const float* __restrict__ bvec,
                          const float* __restrict__ root, __nv_bfloat16* __restrict__ Bb,
                          int cin) {
    int i = blockIdx.x * blockDim.x + threadIdx.x;
    if (i >= NDB * HH * cin) return;
    int t = i / cin, k = i - t * cin;
    int d = t >> 7, o = t & 127;
    float w;
    if (d < ED)       w = W[(size_t)(d * cin + k) * HH + o];
    else if (d == ED) w = bvec[(size_t)k * HH + o];
    else              w = root[(size_t)k * HH + o];
    __nv_bfloat16 b1, b2;
    split2(w, b1, b2);
    __nv_bfloat16* row = Bb + (size_t)t * NSPLIT * cin + k;
    row[0] = b1; row[cin] = b2; row[2 * cin] = b1;
}

// ---------------- raw mma.sync GEMM ----------------
// C[128,128] per block; 8 warps (4 m x 2 n), warp tile 32x64; BK=32; 3-stage cp.async,
// single __syncthreads per chunk. Block x == 33 -> h2 = acc + bias (root slice).
#define SROW 40                // bf16 elems per smem row slot (80B)
#define STG (128 * SROW)       // elems per matrix per stage
#define GEMM_SMEM (3 * 2 * STG * 2)   // 61440 bytes

__global__ __launch_bounds__(256, 2)
void gemm_mma_k(const __nv_bfloat16* __restrict__ Ab, const __nv_bfloat16* __restrict__ Bb,
                float* __restrict__ Y, const float* __restrict__ bias,
                float* __restrict__ h2, int Kp) {
    extern __shared__ __nv_bfloat16 sm[];
    const int tid = threadIdx.x;
    const int lane = tid & 31;
    const int wid = tid >> 5;
    const int warp_m = wid & 3;
    const int warp_n = wid >> 2;
    const int mbase = blockIdx.y * 128;
    const int nbase = blockIdx.x * 128;
    const int NC = Kp >> 5;

    float acc[2][8][4];
#pragma unroll
    for (int i = 0; i < 2; i++)
#pragma unroll
        for (int j = 0; j < 8; j++)
#pragma unroll
            for (int q = 0; q < 4; q++) acc[i][j][q] = 0.f;

    auto prefetch = [&](int cIdx, int s) {
        const int kc = cIdx * 32;
        __nv_bfloat16* base = sm + s * 2 * STG;
#pragma unroll
        for (int u = 0; u < 4; u++) {
            int q = tid + u * 256;          // 0..1023
            int isB = q >> 9;
            int qq = q & 511;
            int r = qq >> 2, ch = qq & 3;
            const __nv_bfloat16* g = isB
                ? (Bb + (size_t)(nbase + r) * Kp + kc + ch * 8)
                : (Ab + (size_t)(mbase + r) * Kp + kc + ch * 8);
            cp_async16(smem_u32(base + isB * STG + r * SROW + ch * 8), g);
        }
        asm volatile("cp.async.commit_group;" ::: "memory");
    };

    prefetch(0, 0);
    prefetch(1, 1);

    for (int c = 0; c < NC; c++) {
        if (c + 1 < NC) asm volatile("cp.async.wait_group 1;" ::: "memory");
        else            asm volatile("cp.async.wait_group 0;" ::: "memory");
        __syncthreads();
        // stage (c+2)%3 == (c-1)%3: retired by all warps at the barrier above
        if (c + 2 < NC) prefetch(c + 2, (c + 2) % 3);

        const int s = c % 3;
        const uint32_t a_base = smem_u32(sm + s * 2 * STG);
        const uint32_t b_base = a_base + STG * 2;   // bytes

#pragma unroll
        for (int kk = 0; kk < 2; kk++) {
            uint32_t a[2][4];
#pragma unroll
            for (int i = 0; i < 2; i++) {
                int arow = warp_m * 32 + i * 16 + (lane & 15);
                int acol = kk * 16 + (lane >> 4) * 8;
                ldsm4(a[i][0], a[i][1], a[i][2], a[i][3],
                      a_base + (uint32_t)(arow * SROW + acol) * 2);
            }
            uint32_t b[8][2];
#pragma unroll
            for (int g = 0; g < 4; g++) {
                int m8 = lane >> 3;          // 0..3
                int nrow = warp_n * 64 + (2 * g + (m8 >> 1)) * 8 + (lane & 7);
                int kcol = kk * 16 + (m8 & 1) * 8;
                ldsm4(b[2 * g][0], b[2 * g][1], b[2 * g + 1][0], b[2 * g + 1][1],
                      b_base + (uint32_t)(nrow * SROW + kcol) * 2);
            }
#pragma unroll
            for (int i = 0; i < 2; i++)
#pragma unroll
                for (int j = 0; j < 8; j++)
                    mma16816(acc[i][j], a[i], b[j]);
        }
    }

    // epilogue
    const int gid = lane >> 2, tig = lane & 3;
    if (blockIdx.x == 33) {
#pragma unroll
        for (int i = 0; i < 2; i++) {
            int row = mbase + warp_m * 32 + i * 16 + gid;
#pragma unroll
            for (int j = 0; j < 8; j++) {
                int col = warp_n * 64 + j * 8 + tig * 2;
                float b0 = bias[col], b1 = bias[col + 1];
                float* d0 = h2 + (size_t)row * HH + col;
                d0[0] = acc[i][j][0] + b0;
                d0[1] = acc[i][j][1] + b1;
                float* d1 = h2 + (size_t)(row + 8) * HH + col;
                d1[0] = acc[i][j][2] + b0;
                d1[1] = acc[i][j][3] + b1;
            }
        }
    } else {
#pragma unroll
        for (int i = 0; i < 2; i++) {
            int row = mbase + warp_m * 32 + i * 16 + gid;
#pragma unroll
            for (int j = 0; j < 8; j++) {
                int col = nbase + warp_n * 64 + j * 8 + tig * 2;
                *reinterpret_cast<float2*>(Y + (size_t)row * YC + col) =
                    make_float2(acc[i][j][0], acc[i][j][1]);
                *reinterpret_cast<float2*>(Y + (size_t)(row + 8) * YC + col) =
                    make_float2(acc[i][j][2], acc[i][j][3]);
            }
        }
    }
}

// ---------------- pipeline kernels ----------------
__global__ void init_edges_k(const int* __restrict__ ei, int* __restrict__ src,
                             int* __restrict__ dst, int* __restrict__ valid) {
    int e = blockIdx.x * blockDim.x + threadIdx.x;
    if (e < NE) { src[e] = ei[e]; dst[e] = ei[NE + e]; valid[e] = 1; }
}

// warp-per-edge, float4 lanes, coefficients via shuffle (no smem / block sync)
__global__ void edge_msg_k(const float* __restrict__ ea, const float* __restrict__ y,
                           float* __restrict__ agg, const int* __restrict__ src,
                           const int* __restrict__ dst, const int* __restrict__ valid) {
    int e = blockIdx.x * 4 + (threadIdx.x >> 5);
    int lane = threadIdx.x & 31;
    if (!valid[e]) return;
    float av = ea[(size_t)e * ED + lane];          // lane d holds a[e,d]
    const float4* yr = reinterpret_cast<const float4*>(y + (size_t)src[e] * YC) + lane;
    float4 acc = make_float4(0.f, 0.f, 0.f, 0.f);
#pragma unroll
    for (int d = 0; d < ED; d++) {
        float ad = __shfl_sync(0xffffffffu, av, d);
        float4 v = yr[d * 32];
        acc.x = fmaf(ad, v.x, acc.x);
        acc.y = fmaf(ad, v.y, acc.y);
        acc.z = fmaf(ad, v.z, acc.z);
        acc.w = fmaf(ad, v.w, acc.w);
    }
    {   // bias slice d=32, coefficient 1
        float4 v = yr[ED * 32];
        acc.x += v.x; acc.y += v.y; acc.z += v.z; acc.w += v.w;
    }
    float* ag = agg + (size_t)dst[e] * HH + lane * 4;
    atomicAdd(ag + 0, acc.x);
    atomicAdd(ag + 1, acc.y);
    atomicAdd(ag + 2, acc.z);
    atomicAdd(ag + 3, acc.w);
}

// deterministic BN partials: block j sums rows j, j+64, ...
__global__ void bn_stats_k(const float* __restrict__ h, float* __restrict__ partial, int n) {
    int j = blockIdx.x, o = threadIdx.x;
    float s = 0.f, s2 = 0.f;
    for (int r = j; r < n; r += 64) {
        float v = h[(size_t)r * HH + o];
        s += v; s2 += v * v;
    }
    partial[j * 256 + o] = s;
    partial[j * 256 + 128 + o] = s2;
}

// fused: BN apply + ReLU + score + topk + gather(+scale) + split-A + edge remap.
__global__ void fused_pool_k(const float* __restrict__ h2, const float* __restrict__ partial,
                             const float* __restrict__ gamma, const float* __restrict__ beta,
                             const float* __restrict__ pw,
                             float* __restrict__ hout, __nv_bfloat16* __restrict__ Ab,
                             int* __restrict__ src, int* __restrict__ dst,
                             int* __restrict__ valid,
                             int npg, int kk, int n) {
    extern __shared__ float fs[];
    float* tile = fs;                       // npg * 129
    float* spw  = tile + npg * 129;         // 128
    float* sc   = spw + 128;                // npg
    float* red  = sc + npg;                 // 128
    int*   rankA = (int*)(red + 128);       // npg

    const int b = blockIdx.x, o = threadIdx.x;
    const int base = b * npg;

    float s = 0.f, s2 = 0.f;
#pragma unroll 8
    for (int j = 0; j < 64; j++) {
        s  += partial[j * 256 + o];
        s2 += partial[j * 256 + 128 + o];
    }
    float inv_n = 1.f / (float)n;
    float mu = s * inv_n;
    float var = s2 * inv_n - mu * mu;
    float scal = gamma[o] * rsqrtf(var + 1e-5f);
    float be = beta[o];

    float pwo = pw[o];
    spw[o] = pwo;
    red[o] = pwo * pwo;
    __syncthreads();
    for (int st = 64; st > 0; st >>= 1) {
        if (o < st) red[o] += red[o + st];
        __syncthreads();
    }
    float pwn = sqrtf(red[0]);

    for (int i = 0; i < npg; i++) {
        float v = h2[(size_t)(base + i) * HH + o];
        tile[i * 129 + o] = fmaxf(scal * (v - mu) + be, 0.f);
    }
    __syncthreads();

    if (o < npg) {
        float acc = 0.f;
#pragma unroll 16
        for (int c = 0; c < HH; c++) acc += tile[o * 129 + c] * spw[c];
        sc[o] = tanhf(acc / pwn);
    }
    __syncthreads();

    if (o < npg) {
        float mine = sc[o];
        int r = 0;
        for (int j = 0; j < npg; j++) {
            float sj = sc[j];
            r += (sj > mine) || (sj == mine && j < o);
        }
        rankA[o] = r;
    }
    __syncthreads();

    for (int i = 0; i < npg; i++) {
        int r = rankA[i];
        if (r < kk) {
            int nid = b * kk + r;
            float val = tile[i * 129 + o] * sc[i];
            hout[(size_t)nid * HH + o] = val;
            __nv_bfloat16 h1, h2b;
            split2(val, h1, h2b);
            __nv_bfloat16* row = Ab + (size_t)nid * (NSPLIT * HH) + o;
            row[0] = h1; row[HH] = h1; row[2 * HH] = h2b;
        }
    }

    for (int e = b * EPG + o; e < (b + 1) * EPG; e += 128) {
        if (valid[e]) {
            int rs = rankA[src[e] - base];
            int rd = rankA[dst[e] - base];
            if (rs < kk && rd < kk) { src[e] = b * kk + rs; dst[e] = b * kk + rd; }
            else valid[e] = 0;
        }
    }
}

// fused meanpool + 2-layer MLP + sigmoid; one block per graph, 128 threads
__global__ void readout_k(const float* __restrict__ h, const float* __restrict__ w1,
                          const float* __restrict__ b1, const float* __restrict__ w2,
                          const float* __restrict__ b2, float* __restrict__ out) {
    __shared__ float sg[HH];
    __shared__ float red[64];
    int b = blockIdx.x, o = threadIdx.x;
    float acc = 0.f;
#pragma unroll
    for (int i = 0; i < K3; i++) acc += h[(size_t)(b * K3 + i) * HH + o];
    sg[o] = acc * (1.f / K3);
    __syncthreads();
    if (o < 64) {
        float a = b1[o];
        for (int i = 0; i < HH; i++) a = fmaf(sg[i], w1[i * 64 + o], a);
        a = fmaxf(a, 0.f);
        red[o] = a * w2[o];
    }
    __syncthreads();
    for (int st = 32; st > 0; st >>= 1) {
        if (o < st) red[o] += red[o + st];
        __syncthreads();
    }
    if (o == 0) out[b] = 1.f / (1.f + expf(-(red[0] + b2[0])));
}

// ---------------- host ----------------
extern "C" void kernel_launch(void* const* d_in, const int* in_sizes, int n_in,
                              void* d_out, int out_size) {
    const float* x     = (const float*)d_in[0];
    const int*   ei    = (const int*)d_in[1];
    const float* ea    = (const float*)d_in[2];
    const float* nn1_w = (const float*)d_in[4];
    const float* nn1_b = (const float*)d_in[5];
    const float* root1 = (const float*)d_in[6];
    const float* bias1 = (const float*)d_in[7];
    const float* nn2_w = (const float*)d_in[8];
    const float* nn2_b = (const float*)d_in[9];
    const float* root2 = (const float*)d_in[10];
    const float* bias2 = (const float*)d_in[11];
    const float* nn3_w = (const float*)d_in[12];
    const float* nn3_b = (const float*)d_in[13];
    const float* root3 = (const float*)d_in[14];
    const float* bias3 = (const float*)d_in[15];
    const float* gamma1 = (const float*)d_in[16];
    const float* beta1  = (const float*)d_in[17];
    const float* gamma2 = (const float*)d_in[18];
    const float* beta2  = (const float*)d_in[19];
    const float* gamma3 = (const float*)d_in[20];
    const float* beta3  = (const float*)d_in[21];
    const float* pw1 = (const float*)d_in[22];
    const float* pw2 = (const float*)d_in[23];
    const float* pw3 = (const float*)d_in[24];
    const float* l1w = (const float*)d_in[25];
    const float* l1b = (const float*)d_in[26];
    const float* l2w = (const float*)d_in[27];
    const float* l2b = (const float*)d_in[28];
    float* out = (float*)d_out;

    float *yp, *hp, *h2p, *partp;
    __nv_bfloat16 *Abp, *Bbp;
    int *srcp, *dstp, *validp;
    cudaGetSymbolAddress((void**)&yp, g_y);
    cudaGetSymbolAddress((void**)&Abp, g_Ab);
    cudaGetSymbolAddress((void**)&Bbp, g_Bb);
    cudaGetSymbolAddress((void**)&hp, g_h);
    cudaGetSymbolAddress((void**)&h2p, g_h2);
    cudaGetSymbolAddress((void**)&partp, g_partial);
    cudaGetSymbolAddress((void**)&srcp, g_src);
    cudaGetSymbolAddress((void**)&dstp, g_dst);
    cudaGetSymbolAddress((void**)&validp, g_valid);

    cudaFuncSetAttribute(gemm_mma_k, cudaFuncAttributeMaxDynamicSharedMemorySize, GEMM_SMEM);
    const int POOL_SMEM = (NPG0 * 129 + 128 + 2 * NPG0 + 128) * 4;
    cudaFuncSetAttribute(fused_pool_k, cudaFuncAttributeMaxDynamicSharedMemorySize, POOL_SMEM);

    init_edges_k<<<(NE + 255) / 256, 256>>>(ei, srcp, dstp, validp);

    // ---- layer 1: n=4096, cin=64, Kp=192 ----
    split_A_k<<<(NN0 * CIN0 + 255) / 256, 256>>>(x, Abp, NN0, CIN0);
    split_B_k<<<(NDB * HH * CIN0 + 255) / 256, 256>>>(nn1_w, nn1_b, root1, Bbp, CIN0);
    gemm_mma_k<<<dim3(NDB, NN0 / 128), 256, GEMM_SMEM>>>(Abp, Bbp, yp, bias1, h2p,
                                                         NSPLIT * CIN0);
    edge_msg_k<<<NE / 4, 128>>>(ea, yp, h2p, srcp, dstp, validp);
    bn_stats_k<<<64, HH>>>(h2p, partp, NN0);
    fused_pool_k<<<NB, HH, (NPG0 * 129 + 128 + 2 * NPG0 + 128) * 4>>>(
        h2p, partp, gamma1, beta1, pw1, hp, Abp, srcp, dstp, validp, NPG0, K1, NN0);

    // ---- layer 2: n=2048, cin=128, Kp=384 ----
    int n2 = NB * K1;
    split_B_k<<<(NDB * HH * HH + 255) / 256, 256>>>(nn2_w, nn2_b, root2, Bbp, HH);
    gemm_mma_k<<<dim3(NDB, n2 / 128), 256, GEMM_SMEM>>>(Abp, Bbp, yp, bias2, h2p,
                                                        NSPLIT * HH);
    edge_msg_k<<<NE / 4, 128>>>(ea, yp, h2p, srcp, dstp, validp);
    bn_stats_k<<<64, HH>>>(h2p, partp, n2);
    fused_pool_k<<<NB, HH, (K1 * 129 + 128 + 2 * K1 + 128) * 4>>>(
        h2p, partp, gamma2, beta2, pw2, hp, Abp, srcp, dstp, validp, K1, K2, n2);

    // ---- layer 3: n=1024, cin=128, Kp=384 ----
    int n3 = NB * K2;
    split_B_k<<<(NDB * HH * HH + 255) / 256, 256>>>(nn3_w, nn3_b, root3, Bbp, HH);
    gemm_mma_k<<<dim3(NDB, n3 / 128), 256, GEMM_SMEM>>>(Abp, Bbp, yp, bias3, h2p,
                                                        NSPLIT * HH);
    edge_msg_k<<<NE / 4, 128>>>(ea, yp, h2p, srcp, dstp, validp);
    bn_stats_k<<<64, HH>>>(h2p, partp, n3);
    fused_pool_k<<<NB, HH, (K2 * 129 + 128 + 2 * K2 + 128) * 4>>>(
        h2p, partp, gamma3, beta3, pw3, hp, Abp, srcp, dstp, validp, K2, K3, n3);

    // ---- readout ----
    readout_k<<<NB, HH>>>(hp, l1w, l1b, l2w, l2b, out);
}

// round 7
// speedup vs baseline: 2.5936x; 1.0103x over previous
#include <cuda_runtime.h>
#include <cuda_bf16.h>
#include <math.h>
#include <stdint.h>

// Problem constants
#define NB   32
#define NPG0 128
#define NE   8192
#define EPG  (NE/NB)      // 256 edges per graph (contiguous)
#define CIN0 64
#define ED   32
#define HH   128
#define CED  33           // 32 edge-feature slices + bias slice
#define NDB  34           // + root slice (diverted to h2 in epilogue)
#define YC   (CED*HH)     // 4224 (Y stride; root slice not stored)
#define K1   64
#define K2   32
#define K3   16
#define NN0  (NB*NPG0)    // 4096
#define NSPLIT 3

// ---------------- scratch ----------------
__device__ float g_y[NN0 * YC];                       // 69 MB
__device__ __nv_bfloat16 g_Ab[NN0 * NSPLIT * HH];
__device__ __nv_bfloat16 g_Bb[(NDB * HH) * NSPLIT * HH];
__device__ float g_h[NN0 * HH];
__device__ float g_h2[NN0 * HH];
__device__ int   g_src[NE], g_dst[NE], g_valid[NE];
__device__ float g_partial[64 * 256];

// ---------------- helpers ----------------
__device__ __forceinline__ void split2(float x, __nv_bfloat16& h1, __nv_bfloat16& h2) {
    h1 = __float2bfloat16(x);
    h2 = __float2bfloat16(x - __bfloat162float(h1));
}
__device__ __forceinline__ uint32_t smem_u32(const void* p) {
    return (uint32_t)__cvta_generic_to_shared(p);
}
__device__ __forceinline__ void cp_async16(uint32_t saddr, const void* gaddr) {
    asm volatile("cp.async.cg.shared.global [%0], [%1], 16;" :: "r"(saddr), "l"(gaddr));
}
__device__ __forceinline__ void ldsm4(uint32_t& r0, uint32_t& r1, uint32_t& r2, uint32_t& r3,
                                      uint32_t addr) {
    asm volatile("ldmatrix.sync.aligned.m8n8.x4.shared.b16 {%0,%1,%2,%3}, [%4];"
                 : "=r"(r0), "=r"(r1), "=r"(r2), "=r"(r3) : "r"(addr));
}
__device__ __forceinline__ void mma16816(float* c, const uint32_t* a, const uint32_t* b) {
    asm volatile("mma.sync.aligned.m16n8k16.row.col.f32.bf16.bf16.f32 "
                 "{%0,%1,%2,%3}, {%4,%5,%6,%7}, {%8,%9}, {%0,%1,%2,%3};"
                 : "+f"(c[0]), "+f"(c[1]), "+f"(c[2]), "+f"(c[3])
                 : "r"(a[0]), "r"(a[1]), "r"(a[2]), "r"(a[3]), "r"(b[0]), "r"(b[1]));
}

// ---------------- split prep ----------------
// Ab[r, j*cin+k], blocks [h1, h1, h2]
__global__ void split_A_k(const float* __restrict__ A, __nv_bfloat16* __restrict__ Ab,
                          int n, int cin) {
    int i = blockIdx.x * blockDim.x + threadIdx.x;
    if (i >= n * cin) return;
    int r = i / cin, k = i - r * cin;
    __nv_bfloat16 h1, h2;
    split2(A[i], h1, h2);
    __nv_bfloat16* row = Ab + (size_t)r * NSPLIT * cin + k;
    row[0] = h1; row[cin] = h1; row[2 * cin] = h2;
}

// BbT[t, j*cin+k], blocks [b1, b2, b1]; t = d*128+o
__global__ void split_B_k(const float* __restrict__ W, const float* __restrict__ bvec,
                          const float* __restrict__ root, __nv_bfloat16* __restrict__ Bb,
                          int cin) {
    int i = blockIdx.x * blockDim.x + threadIdx.x;
    if (i >= NDB * HH * cin) return;
    int t = i / cin, k = i - t * cin;
    int d = t >> 7, o = t & 127;
    float w;
    if (d < ED)       w = W[(size_t)(d * cin + k) * HH + o];
    else if (d == ED) w = bvec[(size_t)k * HH + o];
    else              w = root[(size_t)k * HH + o];
    __nv_bfloat16 b1, b2;
    split2(w, b1, b2);
    __nv_bfloat16* row = Bb + (size_t)t * NSPLIT * cin + k;
    row[0] = b1; row[cin] = b2; row[2 * cin] = b1;
}

// ---------------- raw mma.sync GEMM ----------------
// C[128,128] per block; 16 warps (4m x 4n), warp tile 32x32; BK=64; 3-stage cp.async,
// single __syncthreads per chunk, register-double-buffered frags across kk.
// Block x == 33 -> h2 = acc + bias (root slice).
#define BK   64
#define SROW 72                // 64+8 bf16 per row slot (144B): conflict-free ldsm
#define STG  (128 * SROW)      // elems per matrix per stage
#define GEMM_SMEM (3 * 2 * STG * 2)   // 110592 bytes

__global__ __launch_bounds__(512, 2)
void gemm_mma_k(const __nv_bfloat16* __restrict__ Ab, const __nv_bfloat16* __restrict__ Bb,
                float* __restrict__ Y, const float* __restrict__ bias,
                float* __restrict__ h2, int Kp) {
    extern __shared__ __nv_bfloat16 sm[];
    const int tid = threadIdx.x;
    const int lane = tid & 31;
    const int wid = tid >> 5;
    const int warp_m = wid & 3;     // 0..3
    const int warp_n = wid >> 2;    // 0..3
    const int mbase = blockIdx.y * 128;
    const int nbase = blockIdx.x * 128;
    const int NC = Kp >> 6;         // BK=64 chunks (Kp = 192 or 384)

    float acc[2][4][4];
#pragma unroll
    for (int i = 0; i < 2; i++)
#pragma unroll
        for (int j = 0; j < 4; j++)
#pragma unroll
            for (int q = 0; q < 4; q++) acc[i][j][q] = 0.f;

    // prefetch one BK=64 tile-pair into stage s (2048 16B-chunks, 4 per thread)
    auto prefetch = [&](int cIdx, int s) {
        const int kc = cIdx * BK;
        __nv_bfloat16* base = sm + s * 2 * STG;
#pragma unroll
        for (int u = 0; u < 4; u++) {
            int q = tid + u * 512;           // 0..2047
            int isB = q >> 10;
            int qq = q & 1023;
            int r = qq >> 3, ch = qq & 7;
            const __nv_bfloat16* g = isB
                ? (Bb + (size_t)(nbase + r) * Kp + kc + ch * 8)
                : (Ab + (size_t)(mbase + r) * Kp + kc + ch * 8);
            cp_async16(smem_u32(base + isB * STG + r * SROW + ch * 8), g);
        }
        asm volatile("cp.async.commit_group;" ::: "memory");
    };

    prefetch(0, 0);
    if (NC > 1) prefetch(1, 1);

    for (int c = 0; c < NC; c++) {
        if (c + 1 < NC) asm volatile("cp.async.wait_group 1;" ::: "memory");
        else            asm volatile("cp.async.wait_group 0;" ::: "memory");
        __syncthreads();
        if (c + 2 < NC) prefetch(c + 2, (c + 2) % 3);

        const int s = c % 3;
        const uint32_t a_base = smem_u32(sm + s * 2 * STG);
        const uint32_t b_base = a_base + STG * 2;   // bytes

        uint32_t af[2][2][4];   // [buf][i][4]
        uint32_t bf[2][4][2];   // [buf][j][2]

        auto load_frags = [&](int kk, int buf) {
            int acol = kk * 16 + (lane >> 4) * 8;
#pragma unroll
            for (int i = 0; i < 2; i++) {
                int arow = warp_m * 32 + i * 16 + (lane & 15);
                ldsm4(af[buf][i][0], af[buf][i][1], af[buf][i][2], af[buf][i][3],
                      a_base + (uint32_t)(arow * SROW + acol) * 2);
            }
            int m8 = lane >> 3;
            int kcol = kk * 16 + (m8 & 1) * 8;
#pragma unroll
            for (int g = 0; g < 2; g++) {
                int nrow = warp_n * 32 + (2 * g + (m8 >> 1)) * 8 + (lane & 7);
                ldsm4(bf[buf][2 * g][0], bf[buf][2 * g][1],
                      bf[buf][2 * g + 1][0], bf[buf][2 * g + 1][1],
                      b_base + (uint32_t)(nrow * SROW + kcol) * 2);
            }
        };

        load_frags(0, 0);
#pragma unroll
        for (int kk = 0; kk < 4; kk++) {
            int cur = kk & 1;
            if (kk < 3) load_frags(kk + 1, cur ^ 1);
#pragma unroll
            for (int i = 0; i < 2; i++)
#pragma unroll
                for (int j = 0; j < 4; j++)
                    mma16816(acc[i][j], af[cur][i], bf[cur][j]);
        }
    }

    // epilogue: c-frag: {c0,c1}=C[gid][tig*2..+1], {c2,c3}=C[gid+8][tig*2..+1]
    const int gid = lane >> 2, tig = lane & 3;
    if (blockIdx.x == 33) {
#pragma unroll
        for (int i = 0; i < 2; i++) {
            int row = mbase + warp_m * 32 + i * 16 + gid;
#pragma unroll
            for (int j = 0; j < 4; j++) {
                int col = warp_n * 32 + j * 8 + tig * 2;
                float b0 = bias[col], b1 = bias[col + 1];
                float* d0 = h2 + (size_t)row * HH + col;
                d0[0] = acc[i][j][0] + b0;
                d0[1] = acc[i][j][1] + b1;
                float* d1 = h2 + (size_t)(row + 8) * HH + col;
                d1[0] = acc[i][j][2] + b0;
                d1[1] = acc[i][j][3] + b1;
            }
        }
    } else {
#pragma unroll
        for (int i = 0; i < 2; i++) {
            int row = mbase + warp_m * 32 + i * 16 + gid;
#pragma unroll
            for (int j = 0; j < 4; j++) {
                int col = nbase + warp_n * 32 + j * 8 + tig * 2;
                *reinterpret_cast<float2*>(Y + (size_t)row * YC + col) =
                    make_float2(acc[i][j][0], acc[i][j][1]);
                *reinterpret_cast<float2*>(Y + (size_t)(row + 8) * YC + col) =
                    make_float2(acc[i][j][2], acc[i][j][3]);
            }
        }
    }
}

// ---------------- pipeline kernels ----------------
__global__ void init_edges_k(const int* __restrict__ ei, int* __restrict__ src,
                             int* __restrict__ dst, int* __restrict__ valid) {
    int e = blockIdx.x * blockDim.x + threadIdx.x;
    if (e < NE) { src[e] = ei[e]; dst[e] = ei[NE + e]; valid[e] = 1; }
}

// warp-per-edge, float4 lanes, coefficients via shuffle (no smem / block sync)
__global__ void edge_msg_k(const float* __restrict__ ea, const float* __restrict__ y,
                           float* __restrict__ agg, const int* __restrict__ src,
                           const int* __restrict__ dst, const int* __restrict__ valid) {
    int e = blockIdx.x * 4 + (threadIdx.x >> 5);
    int lane = threadIdx.x & 31;
    if (!valid[e]) return;
    float av = ea[(size_t)e * ED + lane];          // lane d holds a[e,d]
    const float4* yr = reinterpret_cast<const float4*>(y + (size_t)src[e] * YC) + lane;
    float4 acc = make_float4(0.f, 0.f, 0.f, 0.f);
#pragma unroll
    for (int d = 0; d < ED; d++) {
        float ad = __shfl_sync(0xffffffffu, av, d);
        float4 v = yr[d * 32];
        acc.x = fmaf(ad, v.x, acc.x);
        acc.y = fmaf(ad, v.y, acc.y);
        acc.z = fmaf(ad, v.z, acc.z);
        acc.w = fmaf(ad, v.w, acc.w);
    }
    {   // bias slice d=32, coefficient 1
        float4 v = yr[ED * 32];
        acc.x += v.x; acc.y += v.y; acc.z += v.z; acc.w += v.w;
    }
    float* ag = agg + (size_t)dst[e] * HH + lane * 4;
    atomicAdd(ag + 0, acc.x);
    atomicAdd(ag + 1, acc.y);
    atomicAdd(ag + 2, acc.z);
    atomicAdd(ag + 3, acc.w);
}

// deterministic BN partials: block j sums rows j, j+64, ...
__global__ void bn_stats_k(const float* __restrict__ h, float* __restrict__ partial, int n) {
    int j = blockIdx.x, o = threadIdx.x;
    float s = 0.f, s2 = 0.f;
    for (int r = j; r < n; r += 64) {
        float v = h[(size_t)r * HH + o];
        s += v; s2 += v * v;
    }
    partial[j * 256 + o] = s;
    partial[j * 256 + 128 + o] = s2;
}

// fused: BN apply + ReLU + score + topk + gather(+scale) + split-A + edge remap.
__global__ void fused_pool_k(const float* __restrict__ h2, const float* __restrict__ partial,
                             const float* __restrict__ gamma, const float* __restrict__ beta,
                             const float* __restrict__ pw,
                             float* __restrict__ hout, __nv_bfloat16* __restrict__ Ab,
                             int* __restrict__ src, int* __restrict__ dst,
                             int* __restrict__ valid,
                             int npg, int kk, int n) {
    extern __shared__ float fs[];
    float* tile = fs;                       // npg * 129
    float* spw  = tile + npg * 129;         // 128
    float* sc   = spw + 128;                // npg
    float* red  = sc + npg;                 // 128
    int*   rankA = (int*)(red + 128);       // npg

    const int b = blockIdx.x, o = threadIdx.x;
    const int base = b * npg;

    float s = 0.f, s2 = 0.f;
#pragma unroll 8
    for (int j = 0; j < 64; j++) {
        s  += partial[j * 256 + o];
        s2 += partial[j * 256 + 128 + o];
    }
    float inv_n = 1.f / (float)n;
    float mu = s * inv_n;
    float var = s2 * inv_n - mu * mu;
    float scal = gamma[o] * rsqrtf(var + 1e-5f);
    float be = beta[o];

    float pwo = pw[o];
    spw[o] = pwo;
    red[o] = pwo * pwo;
    __syncthreads();
    for (int st = 64; st > 0; st >>= 1) {
        if (o < st) red[o] += red[o + st];
        __syncthreads();
    }
    float pwn = sqrtf(red[0]);

    for (int i = 0; i < npg; i++) {
        float v = h2[(size_t)(base + i) * HH + o];
        tile[i * 129 + o] = fmaxf(scal * (v - mu) + be, 0.f);
    }
    __syncthreads();

    if (o < npg) {
        float acc = 0.f;
#pragma unroll 16
        for (int c = 0; c < HH; c++) acc += tile[o * 129 + c] * spw[c];
        sc[o] = tanhf(acc / pwn);
    }
    __syncthreads();

    if (o < npg) {
        float mine = sc[o];
        int r = 0;
        for (int j = 0; j < npg; j++) {
            float sj = sc[j];
            r += (sj > mine) || (sj == mine && j < o);
        }
        rankA[o] = r;
    }
    __syncthreads();

    for (int i = 0; i < npg; i++) {
        int r = rankA[i];
        if (r < kk) {
            int nid = b * kk + r;
            float val = tile[i * 129 + o] * sc[i];
            hout[(size_t)nid * HH + o] = val;
            __nv_bfloat16 h1, h2b;
            split2(val, h1, h2b);
            __nv_bfloat16* row = Ab + (size_t)nid * (NSPLIT * HH) + o;
            row[0] = h1; row[HH] = h1; row[2 * HH] = h2b;
        }
    }

    for (int e = b * EPG + o; e < (b + 1) * EPG; e += 128) {
        if (valid[e]) {
            int rs = rankA[src[e] - base];
            int rd = rankA[dst[e] - base];
            if (rs < kk && rd < kk) { src[e] = b * kk + rs; dst[e] = b * kk + rd; }
            else valid[e] = 0;
        }
    }
}

// fused meanpool + 2-layer MLP + sigmoid; one block per graph, 128 threads
__global__ void readout_k(const float* __restrict__ h, const float* __restrict__ w1,
                          const float* __restrict__ b1, const float* __restrict__ w2,
                          const float* __restrict__ b2, float* __restrict__ out) {
    __shared__ float sg[HH];
    __shared__ float red[64];
    int b = blockIdx.x, o = threadIdx.x;
    float acc = 0.f;
#pragma unroll
    for (int i = 0; i < K3; i++) acc += h[(size_t)(b * K3 + i) * HH + o];
    sg[o] = acc * (1.f / K3);
    __syncthreads();
    if (o < 64) {
        float a = b1[o];
        for (int i = 0; i < HH; i++) a = fmaf(sg[i], w1[i * 64 + o], a);
        a = fmaxf(a, 0.f);
        red[o] = a * w2[o];
    }
    __syncthreads();
    for (int st = 32; st > 0; st >>= 1) {
        if (o < st) red[o] += red[o + st];
        __syncthreads();
    }
    if (o == 0) out[b] = 1.f / (1.f + expf(-(red[0] + b2[0])));
}

// ---------------- host ----------------
extern "C" void kernel_launch(void* const* d_in, const int* in_sizes, int n_in,
                              void* d_out, int out_size) {
    const float* x     = (const float*)d_in[0];
    const int*   ei    = (const int*)d_in[1];
    const float* ea    = (const float*)d_in[2];
    const float* nn1_w = (const float*)d_in[4];
    const float* nn1_b = (const float*)d_in[5];
    const float* root1 = (const float*)d_in[6];
    const float* bias1 = (const float*)d_in[7];
    const float* nn2_w = (const float*)d_in[8];
    const float* nn2_b = (const float*)d_in[9];
    const float* root2 = (const float*)d_in[10];
    const float* bias2 = (const float*)d_in[11];
    const float* nn3_w = (const float*)d_in[12];
    const float* nn3_b = (const float*)d_in[13];
    const float* root3 = (const float*)d_in[14];
    const float* bias3 = (const float*)d_in[15];
    const float* gamma1 = (const float*)d_in[16];
    const float* beta1  = (const float*)d_in[17];
    const float* gamma2 = (const float*)d_in[18];
    const float* beta2  = (const float*)d_in[19];
    const float* gamma3 = (const float*)d_in[20];
    const float* beta3  = (const float*)d_in[21];
    const float* pw1 = (const float*)d_in[22];
    const float* pw2 = (const float*)d_in[23];
    const float* pw3 = (const float*)d_in[24];
    const float* l1w = (const float*)d_in[25];
    const float* l1b = (const float*)d_in[26];
    const float* l2w = (const float*)d_in[27];
    const float* l2b = (const float*)d_in[28];
    float* out = (float*)d_out;

    float *yp, *hp, *h2p, *partp;
    __nv_bfloat16 *Abp, *Bbp;
    int *srcp, *dstp, *validp;
    cudaGetSymbolAddress((void**)&yp, g_y);
    cudaGetSymbolAddress((void**)&Abp, g_Ab);
    cudaGetSymbolAddress((void**)&Bbp, g_Bb);
    cudaGetSymbolAddress((void**)&hp, g_h);
    cudaGetSymbolAddress((void**)&h2p, g_h2);
    cudaGetSymbolAddress((void**)&partp, g_partial);
    cudaGetSymbolAddress((void**)&srcp, g_src);
    cudaGetSymbolAddress((void**)&dstp, g_dst);
    cudaGetSymbolAddress((void**)&validp, g_valid);

    cudaFuncSetAttribute(gemm_mma_k, cudaFuncAttributeMaxDynamicSharedMemorySize, GEMM_SMEM);
    const int POOL_SMEM = (NPG0 * 129 + 128 + 2 * NPG0 + 128) * 4;
    cudaFuncSetAttribute(fused_pool_k, cudaFuncAttributeMaxDynamicSharedMemorySize, POOL_SMEM);

    init_edges_k<<<(NE + 255) / 256, 256>>>(ei, srcp, dstp, validp);

    // ---- layer 1: n=4096, cin=64, Kp=192 ----
    split_A_k<<<(NN0 * CIN0 + 255) / 256, 256>>>(x, Abp, NN0, CIN0);
    split_B_k<<<(NDB * HH * CIN0 + 255) / 256, 256>>>(nn1_w, nn1_b, root1, Bbp, CIN0);
    gemm_mma_k<<<dim3(NDB, NN0 / 128), 512, GEMM_SMEM>>>(Abp, Bbp, yp, bias1, h2p,
                                                         NSPLIT * CIN0);
    edge_msg_k<<<NE / 4, 128>>>(ea, yp, h2p, srcp, dstp, validp);
    bn_stats_k<<<64, HH>>>(h2p, partp, NN0);
    fused_pool_k<<<NB, HH, (NPG0 * 129 + 128 + 2 * NPG0 + 128) * 4>>>(
        h2p, partp, gamma1, beta1, pw1, hp, Abp, srcp, dstp, validp, NPG0, K1, NN0);

    // ---- layer 2: n=2048, cin=128, Kp=384 ----
    int n2 = NB * K1;
    split_B_k<<<(NDB * HH * HH + 255) / 256, 256>>>(nn2_w, nn2_b, root2, Bbp, HH);
    gemm_mma_k<<<dim3(NDB, n2 / 128), 512, GEMM_SMEM>>>(Abp, Bbp, yp, bias2, h2p,
                                                        NSPLIT * HH);
    edge_msg_k<<<NE / 4, 128>>>(ea, yp, h2p, srcp, dstp, validp);
    bn_stats_k<<<64, HH>>>(h2p, partp, n2);
    fused_pool_k<<<NB, HH, (K1 * 129 + 128 + 2 * K1 + 128) * 4>>>(
        h2p, partp, gamma2, beta2, pw2, hp, Abp, srcp, dstp, validp, K1, K2, n2);

    // ---- layer 3: n=1024, cin=128, Kp=384 ----
    int n3 = NB * K2;
    split_B_k<<<(NDB * HH * HH + 255) / 256, 256>>>(nn3_w, nn3_b, root3, Bbp, HH);
    gemm_mma_k<<<dim3(NDB, n3 / 128), 512, GEMM_SMEM>>>(Abp, Bbp, yp, bias3, h2p,
                                                        NSPLIT * HH);
    edge_msg_k<<<NE / 4, 128>>>(ea, yp, h2p, srcp, dstp, validp);
    bn_stats_k<<<64, HH>>>(h2p, partp, n3);
    fused_pool_k<<<NB, HH, (K2 * 129 + 128 + 2 * K2 + 128) * 4>>>(
        h2p, partp, gamma3, beta3, pw3, hp, Abp, srcp, dstp, validp, K2, K3, n3);

    // ---- readout ----
    readout_k<<<NB, HH>>>(hp, l1w, l1b, l2w, l2b, out);
}